// round 13
// baseline (speedup 1.0000x reference)
#include <cuda_runtime.h>
#include <cuda_fp16.h>
#include <cstdint>

// GCNLayer_EdgeCat on GB300 — R13: 3 CTAs/SM everywhere.
//   R12 lesson: 3x70KB smem leaves only ~18KB L1D -> ef re-read missed L1.
//   Fix: fill loop re-indexed so each thread loads exactly its epilogue's ef
//   slots; fp16 hi -> sX (MMA input), 16-bit lo residual kept in 16 half2
//   REGISTERS across the mainloop. No ef re-read, no L1 dependence.
//   A/C gather prefetch dropped (R9: neutral) to fit the 85-reg/3-CTA cap.
//   We=[We1;We2;We3], Wn=[Wn1;Wn2]:
//     A=nf@We1+be, C=nf@We3, An=nf@Wn1+bn        (k_node_pre)
//     m=ReLU(A[src]+ef@We2+C[dst]); out2=m+ef    (k_edge, scatter mean)
//     out1=ReLU(An+mean@Wn2)+nf                  (k_node_upd)
//   GEMMs: single fp16 (calibrated rel_err ~1.7e-4, gate 1e-3).

#define H        128
#define NNODE    50000
#define NEDGE    800000
#define BT       64           // rows per tile
#define NT       256          // 8 warps: warp = 16 rows x 64 cols
#define TPB      8            // edge tiles per block (last block: tail guard)
#define NTILES   (NEDGE / BT) // 12500
#define STRIDE   136          // fp16 row stride (272B, LDSM conflict-free)
#define SSTRIDE  136          // f32 stage stride
#define TILE_A   (BT * STRIDE)
#define TILE_W   (H * STRIDE)

__device__ float g_A  [(size_t)NNODE * H];
__device__ float g_C  [(size_t)NNODE * H];
__device__ float g_An [(size_t)NNODE * H];
__device__ float g_sum[(size_t)NNODE * H];
__device__ float g_cnt[NNODE];
// 5 weights (We1,We2,We3,Wn1,Wn2): [k][n] row-major fp16.
__device__ __half g_Wimg[5 * H * H];

// ---------- PTX helpers ----------
__device__ __forceinline__ uint32_t smem_u32(const void* p) {
    return (uint32_t)__cvta_generic_to_shared(p);
}
__device__ __forceinline__ void ldsm_x4(uint32_t a[4], uint32_t addr) {
    asm volatile("ldmatrix.sync.aligned.m8n8.x4.shared.b16 {%0,%1,%2,%3}, [%4];"
                 : "=r"(a[0]), "=r"(a[1]), "=r"(a[2]), "=r"(a[3]) : "r"(addr));
}
__device__ __forceinline__ void ldsm_x4_t(uint32_t b[4], uint32_t addr) {
    asm volatile("ldmatrix.sync.aligned.m8n8.x4.trans.shared.b16 {%0,%1,%2,%3}, [%4];"
                 : "=r"(b[0]), "=r"(b[1]), "=r"(b[2]), "=r"(b[3]) : "r"(addr));
}
__device__ __forceinline__ void mma16816(float c[4], const uint32_t a[4], const uint32_t b[2]) {
    asm volatile("mma.sync.aligned.m16n8k16.row.col.f32.f16.f16.f32 "
                 "{%0,%1,%2,%3}, {%4,%5,%6,%7}, {%8,%9}, {%0,%1,%2,%3};"
                 : "+f"(c[0]), "+f"(c[1]), "+f"(c[2]), "+f"(c[3])
                 : "r"(a[0]), "r"(a[1]), "r"(a[2]), "r"(a[3]), "r"(b[0]), "r"(b[1]));
}
__device__ __forceinline__ void red_add_v4(float* p, float4 v) {
    asm volatile("red.global.add.v4.f32 [%0], {%1, %2, %3, %4};"
                 :: "l"(p), "f"(v.x), "f"(v.y), "f"(v.z), "f"(v.w) : "memory");
}

// Store a float4 as 4 fp16 at element offset off.
__device__ __forceinline__ void store_hi(__half* hi, int off, float4 v) {
    *(__half2*)(hi + off)     = __half2{__float2half_rn(v.x), __float2half_rn(v.y)};
    *(__half2*)(hi + off + 2) = __half2{__float2half_rn(v.z), __float2half_rn(v.w)};
}
__device__ __forceinline__ uint32_t pack_half2(__half a, __half b) {
    __half2 h{a, b};
    return *reinterpret_cast<uint32_t*>(&h);
}
__device__ __forceinline__ float2 unpack_half2(uint32_t u) {
    __half2 h = *reinterpret_cast<__half2*>(&u);
    return make_float2(__half2float(h.x), __half2float(h.y));
}

// 8-warp core: warp tile 16 rows x 64 cols, single-term fp16 (64 MMAs).
// acc[nt][0..1]: row (warp&3)*16 + lane>>2,   col (warp>>2)*64 + nt*8 + (lane&3)*2
// acc[nt][2..3]: row +8, same cols.
__device__ __forceinline__ void mma_core(const __half* sX, const __half* sW,
                                         int lane, int warp, float acc[8][4]) {
    uint32_t x = smem_u32(sX), w = smem_u32(sW);
    int r0 = (warp & 3) * 16, c0 = (warp >> 2) * 64;
    uint32_t aoff = (uint32_t)((r0 + (lane & 15)) * STRIDE + ((lane >> 4) << 3)) * 2;
    uint32_t boff = (uint32_t)((lane & 15) * STRIDE + c0 + ((lane >> 4) << 3)) * 2;
#pragma unroll
    for (int k0 = 0; k0 < H; k0 += 16) {
        uint32_t a[4];
        ldsm_x4(a, x + aoff + k0 * 2);
#pragma unroll
        for (int ntp = 0; ntp < 4; ntp++) {
            uint32_t b[4];
            ldsm_x4_t(b, w + boff + (uint32_t)(k0 * STRIDE + ntp * 16) * 2);
            mma16816(acc[2 * ntp],     a, b + 0);
            mma16816(acc[2 * ntp + 1], a, b + 2);
        }
    }
}

// Stage one 16-row chunk of acc into smem (warps wr==c and wr==c+4 write).
__device__ __forceinline__ void stage_chunk(float* stg, const float acc[8][4],
                                            int c, int wr, int rq, int cb) {
    if (wr == c) {
#pragma unroll
        for (int nt = 0; nt < 8; nt++) {
            int col = cb + nt * 8;
            *(float2*)&stg[rq * SSTRIDE + col] = make_float2(acc[nt][0], acc[nt][1]);
            *(float2*)&stg[(rq + 8) * SSTRIDE + col] = make_float2(acc[nt][2], acc[nt][3]);
        }
    }
}

// Copy a prepped W image ([k][n] 128x128 fp16) into padded smem.
__device__ __forceinline__ void fill_W(__half* sW, int wsel, int t, int nthr) {
    const uint4* w4 = (const uint4*)(g_Wimg + (size_t)wsel * H * H);
    for (int i = t; i < H * H / 8; i += nthr) {       // 2048 uint4
        int row = i >> 4, c8 = (i & 15) * 8;
        *(uint4*)(sW + row * STRIDE + c8) = w4[i];
    }
}

// ---- k_prep: weights -> fp16 [k][n] images (once) ----
__global__ void k_prep(const float* __restrict__ We, const float* __restrict__ Wn) {
    int idx = blockIdx.x * blockDim.x + threadIdx.x;
    if (idx >= 5 * H * H) return;
    int w = idx / (H * H), r = idx % (H * H);
    const float* src = (w < 3) ? (We + w * H * H) : (Wn + (w - 3) * H * H);
    g_Wimg[(size_t)w * H * H + r] = __float2half_rn(src[r]);
}

// ---- k_node_pre: zero sums; A=nf@We1+be, C=nf@We3, An=nf@Wn1+bn ----
__global__ __launch_bounds__(NT, 3)
void k_node_pre(const float* __restrict__ nf,
                const float* __restrict__ be, const float* __restrict__ bn) {
    extern __shared__ __align__(16) __half sm[];
    __half* sX = sm;
    __half* sW = sm + TILE_A;
    float* stage = (float*)(sm + TILE_A + TILE_W);   // 2 x 16 x SSTRIDE
    int t = threadIdx.x, lane = t & 31, warp = t >> 5;
    int nb = blockIdx.x * BT;

    for (int i = t; i < BT * 32; i += NT) {
        int n = nb + (i >> 5);
        if (n < NNODE) ((float4*)g_sum)[(size_t)n * 32 + (i & 31)] = make_float4(0.f, 0.f, 0.f, 0.f);
    }
    if (t < BT && nb + t < NNODE) g_cnt[nb + t] = 0.f;

    for (int i = t; i < BT * 32; i += NT) {
        int n = nb + (i >> 5);
        float4 v = make_float4(0.f, 0.f, 0.f, 0.f);
        if (n < NNODE) v = ((const float4*)nf)[(size_t)n * 32 + (i & 31)];
        store_hi(sX, (i >> 5) * STRIDE + (i & 31) * 4, v);
    }

    const int    wsel[3] = {0, 2, 3};
    float*       Od[3]   = {g_A, g_C, g_An};
    const float* bias[3] = {be, (const float*)0, bn};

    int rq = lane >> 2, cb = (warp >> 2) * 64 + (lane & 3) * 2;
    int wr = warp & 3;
    int lrow = t >> 4, cg = (t & 15) * 8;        // epilogue ownership

    for (int ph = 0; ph < 3; ph++) {
        __syncthreads();                         // prev phase fully consumed
        fill_W(sW, wsel[ph], t, NT);
        __syncthreads();

        float acc[8][4];
#pragma unroll
        for (int i = 0; i < 8; i++) acc[i][0] = acc[i][1] = acc[i][2] = acc[i][3] = 0.f;
        mma_core(sX, sW, lane, warp, acc);

        float* O = Od[ph];
#pragma unroll
        for (int c = 0; c < 4; c++) {
            float* stg = stage + (c & 1) * (16 * SSTRIDE);
            stage_chunk(stg, acc, c, wr, rq, cb);
            __syncthreads();                     // stage(c) ready
            int n = nb + c * 16 + lrow;
            if (n < NNODE) {
                float4 st0 = *(float4*)&stg[lrow * SSTRIDE + cg];
                float4 st1 = *(float4*)&stg[lrow * SSTRIDE + cg + 4];
                if (bias[ph]) {
                    float4 b0 = *(const float4*)&bias[ph][cg];
                    float4 b1 = *(const float4*)&bias[ph][cg + 4];
                    st0.x += b0.x; st0.y += b0.y; st0.z += b0.z; st0.w += b0.w;
                    st1.x += b1.x; st1.y += b1.y; st1.z += b1.z; st1.w += b1.w;
                }
                *(float4*)&O[(size_t)n * H + cg]     = st0;
                *(float4*)&O[(size_t)n * H + cg + 4] = st1;
            }
        }
    }
}

// ---- k_edge: m=ReLU(A[src]+ef@We2+C[dst]); out2=m+ef; scatter mean ----
__global__ __launch_bounds__(NT, 3)
void k_edge(const float* __restrict__ ef,
            const int* __restrict__ src, const int* __restrict__ dst,
            float* __restrict__ out2) {
    extern __shared__ __align__(16) __half sm[];
    __half* sX   = sm;
    __half* sW   = sm + TILE_A;
    int*   s_src = (int*)(sm + TILE_A + TILE_W);
    int*   s_dst = s_src + BT;
    float* stage = (float*)(s_dst + BT);         // 2 x 16 x SSTRIDE
    int t = threadIdx.x, lane = t & 31, warp = t >> 5;

    fill_W(sW, 1, t, NT);                        // We2, resident for all tiles

    int rq = lane >> 2, cb = (warp >> 2) * 64 + (lane & 3) * 2;
    int wr = warp & 3;
    int lrow = t >> 4, c16 = t & 15, cg = c16 * 8;

    int tiles = NTILES - blockIdx.x * TPB;
    if (tiles > TPB) tiles = TPB;

    for (int tt = 0; tt < tiles; tt++) {
        int eb = (blockIdx.x * TPB + tt) * BT;
        if (t < BT) s_src[t] = src[eb + t];
        else if (t < 2 * BT) s_dst[t - BT] = dst[eb + t - BT];

        // Fill sX(hi) with ownership mapping: thread t loads exactly the ef
        // slots its epilogue outputs (rows c*16+lrow, cols [cg, cg+8)).
        // 16-bit lo residuals stay in registers -> exact-enough ef at use,
        // no smem lo image, no L1-dependent re-read.
        const float4* ef4 = (const float4*)(ef + (size_t)eb * H);
        uint32_t lo[16];
#pragma unroll
        for (int c = 0; c < 4; c++) {
            int row = c * 16 + lrow;
#pragma unroll
            for (int j = 0; j < 2; j++) {
                float4 v = ef4[row * 32 + c16 * 2 + j];
                __half h0 = __float2half_rn(v.x), h1 = __float2half_rn(v.y);
                __half h2 = __float2half_rn(v.z), h3 = __float2half_rn(v.w);
                int off = row * STRIDE + cg + j * 4;
                *(__half2*)(sX + off)     = __half2{h0, h1};
                *(__half2*)(sX + off + 2) = __half2{h2, h3};
                lo[c * 4 + j * 2 + 0] = pack_half2(
                    __float2half_rn(v.x - __half2float(h0)),
                    __float2half_rn(v.y - __half2float(h1)));
                lo[c * 4 + j * 2 + 1] = pack_half2(
                    __float2half_rn(v.z - __half2float(h2)),
                    __float2half_rn(v.w - __half2float(h3)));
            }
        }
        __syncthreads();

        float acc[8][4];
#pragma unroll
        for (int i = 0; i < 8; i++) acc[i][0] = acc[i][1] = acc[i][2] = acc[i][3] = 0.f;
        mma_core(sX, sW, lane, warp, acc);

#pragma unroll
        for (int c = 0; c < 4; c++) {
            float* stg = stage + (c & 1) * (16 * SSTRIDE);
            stage_chunk(stg, acc, c, wr, rq, cb);
            __syncthreads();                     // stage(c) ready

            int row = c * 16 + lrow;
            int s = s_src[row], d = s_dst[row];
            if (c16 == 0) atomicAdd(&g_cnt[d], 1.f);

            float4 st0 = *(float4*)&stg[lrow * SSTRIDE + cg];
            float4 st1 = *(float4*)&stg[lrow * SSTRIDE + cg + 4];
            float4 a0 = *(const float4*)&g_A[(size_t)s * H + cg];
            float4 a1 = *(const float4*)&g_A[(size_t)s * H + cg + 4];
            float4 cc0 = *(const float4*)&g_C[(size_t)d * H + cg];
            float4 cc1 = *(const float4*)&g_C[(size_t)d * H + cg + 4];
            float4 m0, m1;
            m0.x = fmaxf(st0.x + a0.x + cc0.x, 0.f);
            m0.y = fmaxf(st0.y + a0.y + cc0.y, 0.f);
            m0.z = fmaxf(st0.z + a0.z + cc0.z, 0.f);
            m0.w = fmaxf(st0.w + a0.w + cc0.w, 0.f);
            m1.x = fmaxf(st1.x + a1.x + cc1.x, 0.f);
            m1.y = fmaxf(st1.y + a1.y + cc1.y, 0.f);
            m1.z = fmaxf(st1.z + a1.z + cc1.z, 0.f);
            m1.w = fmaxf(st1.w + a1.w + cc1.w, 0.f);

            // ef = hi(sX) + lo(regs)
            uint4 uh = *(uint4*)&sX[row * STRIDE + cg];
            const __half2* h2 = (const __half2*)&uh;
            float2 l0 = unpack_half2(lo[c * 4 + 0]);
            float2 l1 = unpack_half2(lo[c * 4 + 1]);
            float2 l2 = unpack_half2(lo[c * 4 + 2]);
            float2 l3 = unpack_half2(lo[c * 4 + 3]);
            float4 o0, o1;
            o0.x = (m0.x + __half2float(h2[0].x)) + l0.x;
            o0.y = (m0.y + __half2float(h2[0].y)) + l0.y;
            o0.z = (m0.z + __half2float(h2[1].x)) + l1.x;
            o0.w = (m0.w + __half2float(h2[1].y)) + l1.y;
            o1.x = (m1.x + __half2float(h2[2].x)) + l2.x;
            o1.y = (m1.y + __half2float(h2[2].y)) + l2.y;
            o1.z = (m1.z + __half2float(h2[3].x)) + l3.x;
            o1.w = (m1.w + __half2float(h2[3].y)) + l3.y;

            *(float4*)&out2[(size_t)(eb + row) * H + cg]     = o0;
            *(float4*)&out2[(size_t)(eb + row) * H + cg + 4] = o1;
            red_add_v4(&g_sum[(size_t)d * H + cg], m0);
            red_add_v4(&g_sum[(size_t)d * H + cg + 4], m1);
        }
        __syncthreads();                         // sX & stage free for next tile
    }
}

// ---- k_node_upd: out1 = ReLU(An + (sum/max(cnt,1))@Wn2) + nf ----
__global__ __launch_bounds__(NT, 3)
void k_node_upd(const float* __restrict__ nf, float* __restrict__ out1) {
    extern __shared__ __align__(16) __half sm[];
    __half* sX = sm;
    __half* sW = sm + TILE_A;
    float* stage = (float*)(sm + TILE_A + TILE_W);
    int t = threadIdx.x, lane = t & 31, warp = t >> 5;
    int nb = blockIdx.x * BT;

    for (int i = t; i < BT * 32; i += NT) {
        int n = nb + (i >> 5);
        float4 v = make_float4(0.f, 0.f, 0.f, 0.f);
        if (n < NNODE) {
            v = ((const float4*)g_sum)[(size_t)n * 32 + (i & 31)];
            float inv = 1.0f / fmaxf(g_cnt[n], 1.0f);
            v.x *= inv; v.y *= inv; v.z *= inv; v.w *= inv;
        }
        store_hi(sX, (i >> 5) * STRIDE + (i & 31) * 4, v);
    }
    fill_W(sW, 4, t, NT);                        // Wn2
    __syncthreads();

    float acc[8][4];
#pragma unroll
    for (int i = 0; i < 8; i++) acc[i][0] = acc[i][1] = acc[i][2] = acc[i][3] = 0.f;
    mma_core(sX, sW, lane, warp, acc);

    int rq = lane >> 2, cb = (warp >> 2) * 64 + (lane & 3) * 2;
    int wr = warp & 3;
    int lrow = t >> 4, cg = (t & 15) * 8;

#pragma unroll
    for (int c = 0; c < 4; c++) {
        float* stg = stage + (c & 1) * (16 * SSTRIDE);
        stage_chunk(stg, acc, c, wr, rq, cb);
        __syncthreads();
        int n = nb + c * 16 + lrow;
        if (n < NNODE) {
            float4 st0 = *(float4*)&stg[lrow * SSTRIDE + cg];
            float4 st1 = *(float4*)&stg[lrow * SSTRIDE + cg + 4];
            float4 an0 = *(const float4*)&g_An[(size_t)n * H + cg];
            float4 an1 = *(const float4*)&g_An[(size_t)n * H + cg + 4];
            float4 nv0 = *(const float4*)&nf[(size_t)n * H + cg];
            float4 nv1 = *(const float4*)&nf[(size_t)n * H + cg + 4];
            float4 o0, o1;
            o0.x = fmaxf(st0.x + an0.x, 0.f) + nv0.x;
            o0.y = fmaxf(st0.y + an0.y, 0.f) + nv0.y;
            o0.z = fmaxf(st0.z + an0.z, 0.f) + nv0.z;
            o0.w = fmaxf(st0.w + an0.w, 0.f) + nv0.w;
            o1.x = fmaxf(st1.x + an1.x, 0.f) + nv1.x;
            o1.y = fmaxf(st1.y + an1.y, 0.f) + nv1.y;
            o1.z = fmaxf(st1.z + an1.z, 0.f) + nv1.z;
            o1.w = fmaxf(st1.w + an1.w, 0.f) + nv1.w;
            *(float4*)&out1[(size_t)n * H + cg]     = o0;
            *(float4*)&out1[(size_t)n * H + cg + 4] = o1;
        }
    }
}

extern "C" void kernel_launch(void* const* d_in, const int* in_sizes, int n_in,
                              void* d_out, int out_size) {
    const float* nf  = (const float*)d_in[0];
    const float* ef  = (const float*)d_in[1];
    const int*   src = (const int*)d_in[2];
    const int*   dst = (const int*)d_in[3];
    const float* We  = (const float*)d_in[4];
    const float* be  = (const float*)d_in[5];
    const float* Wn  = (const float*)d_in[6];
    const float* bn  = (const float*)d_in[7];
    float* out1 = (float*)d_out;                    // [N,H]
    float* out2 = out1 + (size_t)NNODE * H;         // [E,H]

    const int smem_node = (TILE_A + TILE_W) * (int)sizeof(__half)
                        + 2 * 16 * SSTRIDE * (int)sizeof(float);              // 69632
    const int smem_edge = (TILE_A + TILE_W) * (int)sizeof(__half)
                        + 2 * BT * (int)sizeof(int)
                        + 2 * 16 * SSTRIDE * (int)sizeof(float);              // 70144
    cudaFuncSetAttribute(k_node_pre, cudaFuncAttributeMaxDynamicSharedMemorySize, smem_node);
    cudaFuncSetAttribute(k_edge,     cudaFuncAttributeMaxDynamicSharedMemorySize, smem_edge);
    cudaFuncSetAttribute(k_node_upd, cudaFuncAttributeMaxDynamicSharedMemorySize, smem_node);

    k_prep<<<(5 * H * H + 255) / 256, 256>>>(We, Wn);
    k_node_pre<<<(NNODE + BT - 1) / BT, NT, smem_node>>>(nf, be, bn);
    k_edge<<<(NTILES + TPB - 1) / TPB, NT, smem_edge>>>(ef, src, dst, out2);
    k_node_upd<<<(NNODE + BT - 1) / BT, NT, smem_node>>>(nf, out1);
}

// round 14
// speedup vs baseline: 1.1157x; 1.1157x over previous
#include <cuda_runtime.h>
#include <cuda_fp16.h>
#include <cstdint>

// GCNLayer_EdgeCat on GB300 — R14: measured-best hybrid.
//   k_edge   = R11 config (2 CTAs/SM, ef hi+lo smem images)  — best edge.
//   k_node_* = R12 config (3 CTAs/SM)                        — best nodes.
//   We=[We1;We2;We3], Wn=[Wn1;Wn2]:
//     A=nf@We1+be, C=nf@We3, An=nf@Wn1+bn        (k_node_pre)
//     m=ReLU(A[src]+ef@We2+C[dst]); out2=m+ef    (k_edge, scatter mean)
//     out1=ReLU(An+mean@Wn2)+nf                  (k_node_upd)
//   GEMMs: single fp16 (calibrated rel_err ~1.7e-4, gate 1e-3).

#define H        128
#define NNODE    50000
#define NEDGE    800000
#define BT       64           // rows per tile
#define NT       256          // 8 warps: warp = 16 rows x 64 cols
#define TPB      8            // edge tiles per block (last block: tail guard)
#define NTILES   (NEDGE / BT) // 12500
#define STRIDE   136          // fp16 row stride (272B, LDSM conflict-free)
#define SSTRIDE  136          // f32 stage stride
#define TILE_A   (BT * STRIDE)
#define TILE_W   (H * STRIDE)

__device__ float g_A  [(size_t)NNODE * H];
__device__ float g_C  [(size_t)NNODE * H];
__device__ float g_An [(size_t)NNODE * H];
__device__ float g_sum[(size_t)NNODE * H];
__device__ float g_cnt[NNODE];
// 5 weights (We1,We2,We3,Wn1,Wn2): [k][n] row-major fp16.
__device__ __half g_Wimg[5 * H * H];

// ---------- PTX helpers ----------
__device__ __forceinline__ uint32_t smem_u32(const void* p) {
    return (uint32_t)__cvta_generic_to_shared(p);
}
__device__ __forceinline__ void ldsm_x4(uint32_t a[4], uint32_t addr) {
    asm volatile("ldmatrix.sync.aligned.m8n8.x4.shared.b16 {%0,%1,%2,%3}, [%4];"
                 : "=r"(a[0]), "=r"(a[1]), "=r"(a[2]), "=r"(a[3]) : "r"(addr));
}
__device__ __forceinline__ void ldsm_x4_t(uint32_t b[4], uint32_t addr) {
    asm volatile("ldmatrix.sync.aligned.m8n8.x4.trans.shared.b16 {%0,%1,%2,%3}, [%4];"
                 : "=r"(b[0]), "=r"(b[1]), "=r"(b[2]), "=r"(b[3]) : "r"(addr));
}
__device__ __forceinline__ void mma16816(float c[4], const uint32_t a[4], const uint32_t b[2]) {
    asm volatile("mma.sync.aligned.m16n8k16.row.col.f32.f16.f16.f32 "
                 "{%0,%1,%2,%3}, {%4,%5,%6,%7}, {%8,%9}, {%0,%1,%2,%3};"
                 : "+f"(c[0]), "+f"(c[1]), "+f"(c[2]), "+f"(c[3])
                 : "r"(a[0]), "r"(a[1]), "r"(a[2]), "r"(a[3]), "r"(b[0]), "r"(b[1]));
}
__device__ __forceinline__ void red_add_v4(float* p, float4 v) {
    asm volatile("red.global.add.v4.f32 [%0], {%1, %2, %3, %4};"
                 :: "l"(p), "f"(v.x), "f"(v.y), "f"(v.z), "f"(v.w) : "memory");
}

// Store a float4 as 4 fp16 at element offset off.
__device__ __forceinline__ void store_hi(__half* hi, int off, float4 v) {
    *(__half2*)(hi + off)     = __half2{__float2half_rn(v.x), __float2half_rn(v.y)};
    *(__half2*)(hi + off + 2) = __half2{__float2half_rn(v.z), __float2half_rn(v.w)};
}
// Store hi + residual lo (k_edge only: lo used for exact ef reconstruction).
__device__ __forceinline__ void split_store(__half* hi, __half* lo, int off, float4 v) {
    __half h0 = __float2half_rn(v.x), h1 = __float2half_rn(v.y);
    __half h2 = __float2half_rn(v.z), h3 = __float2half_rn(v.w);
    *(__half2*)(hi + off)     = __half2{h0, h1};
    *(__half2*)(hi + off + 2) = __half2{h2, h3};
    *(__half2*)(lo + off)     = __half2{__float2half_rn(v.x - __half2float(h0)),
                                        __float2half_rn(v.y - __half2float(h1))};
    *(__half2*)(lo + off + 2) = __half2{__float2half_rn(v.z - __half2float(h2)),
                                        __float2half_rn(v.w - __half2float(h3))};
}

// 8-warp core: warp tile 16 rows x 64 cols, single-term fp16 (64 MMAs).
// acc[nt][0..1]: row (warp&3)*16 + lane>>2,   col (warp>>2)*64 + nt*8 + (lane&3)*2
// acc[nt][2..3]: row +8, same cols.
__device__ __forceinline__ void mma_core(const __half* sX, const __half* sW,
                                         int lane, int warp, float acc[8][4]) {
    uint32_t x = smem_u32(sX), w = smem_u32(sW);
    int r0 = (warp & 3) * 16, c0 = (warp >> 2) * 64;
    uint32_t aoff = (uint32_t)((r0 + (lane & 15)) * STRIDE + ((lane >> 4) << 3)) * 2;
    uint32_t boff = (uint32_t)((lane & 15) * STRIDE + c0 + ((lane >> 4) << 3)) * 2;
#pragma unroll
    for (int k0 = 0; k0 < H; k0 += 16) {
        uint32_t a[4];
        ldsm_x4(a, x + aoff + k0 * 2);
#pragma unroll
        for (int ntp = 0; ntp < 4; ntp++) {
            uint32_t b[4];
            ldsm_x4_t(b, w + boff + (uint32_t)(k0 * STRIDE + ntp * 16) * 2);
            mma16816(acc[2 * ntp],     a, b + 0);
            mma16816(acc[2 * ntp + 1], a, b + 2);
        }
    }
}

// Stage one 16-row chunk of acc into smem (warps wr==c and wr==c+4 write).
__device__ __forceinline__ void stage_chunk(float* stg, const float acc[8][4],
                                            int c, int wr, int rq, int cb) {
    if (wr == c) {
#pragma unroll
        for (int nt = 0; nt < 8; nt++) {
            int col = cb + nt * 8;
            *(float2*)&stg[rq * SSTRIDE + col] = make_float2(acc[nt][0], acc[nt][1]);
            *(float2*)&stg[(rq + 8) * SSTRIDE + col] = make_float2(acc[nt][2], acc[nt][3]);
        }
    }
}

// Copy a prepped W image ([k][n] 128x128 fp16) into padded smem.
__device__ __forceinline__ void fill_W(__half* sW, int wsel, int t, int nthr) {
    const uint4* w4 = (const uint4*)(g_Wimg + (size_t)wsel * H * H);
    for (int i = t; i < H * H / 8; i += nthr) {       // 2048 uint4
        int row = i >> 4, c8 = (i & 15) * 8;
        *(uint4*)(sW + row * STRIDE + c8) = w4[i];
    }
}

// ---- k_prep: weights -> fp16 [k][n] images (once) ----
__global__ void k_prep(const float* __restrict__ We, const float* __restrict__ Wn) {
    int idx = blockIdx.x * blockDim.x + threadIdx.x;
    if (idx >= 5 * H * H) return;
    int w = idx / (H * H), r = idx % (H * H);
    const float* src = (w < 3) ? (We + w * H * H) : (Wn + (w - 3) * H * H);
    g_Wimg[(size_t)w * H * H + r] = __float2half_rn(src[r]);
}

// ---- k_node_pre: zero sums; A=nf@We1+be, C=nf@We3, An=nf@Wn1+bn (3 CTA/SM) ----
__global__ __launch_bounds__(NT, 3)
void k_node_pre(const float* __restrict__ nf,
                const float* __restrict__ be, const float* __restrict__ bn) {
    extern __shared__ __align__(16) __half sm[];
    __half* sX = sm;
    __half* sW = sm + TILE_A;
    float* stage = (float*)(sm + TILE_A + TILE_W);   // 2 x 16 x SSTRIDE
    int t = threadIdx.x, lane = t & 31, warp = t >> 5;
    int nb = blockIdx.x * BT;

    for (int i = t; i < BT * 32; i += NT) {
        int n = nb + (i >> 5);
        if (n < NNODE) ((float4*)g_sum)[(size_t)n * 32 + (i & 31)] = make_float4(0.f, 0.f, 0.f, 0.f);
    }
    if (t < BT && nb + t < NNODE) g_cnt[nb + t] = 0.f;

    for (int i = t; i < BT * 32; i += NT) {
        int n = nb + (i >> 5);
        float4 v = make_float4(0.f, 0.f, 0.f, 0.f);
        if (n < NNODE) v = ((const float4*)nf)[(size_t)n * 32 + (i & 31)];
        store_hi(sX, (i >> 5) * STRIDE + (i & 31) * 4, v);
    }

    const int    wsel[3] = {0, 2, 3};
    float*       Od[3]   = {g_A, g_C, g_An};
    const float* bias[3] = {be, (const float*)0, bn};

    int rq = lane >> 2, cb = (warp >> 2) * 64 + (lane & 3) * 2;
    int wr = warp & 3;
    int lrow = t >> 4, cg = (t & 15) * 8;        // epilogue ownership

    for (int ph = 0; ph < 3; ph++) {
        __syncthreads();                         // prev phase fully consumed
        fill_W(sW, wsel[ph], t, NT);
        __syncthreads();

        float acc[8][4];
#pragma unroll
        for (int i = 0; i < 8; i++) acc[i][0] = acc[i][1] = acc[i][2] = acc[i][3] = 0.f;
        mma_core(sX, sW, lane, warp, acc);

        float* O = Od[ph];
#pragma unroll
        for (int c = 0; c < 4; c++) {
            float* stg = stage + (c & 1) * (16 * SSTRIDE);
            stage_chunk(stg, acc, c, wr, rq, cb);
            __syncthreads();                     // stage(c) ready
            int n = nb + c * 16 + lrow;
            if (n < NNODE) {
                float4 st0 = *(float4*)&stg[lrow * SSTRIDE + cg];
                float4 st1 = *(float4*)&stg[lrow * SSTRIDE + cg + 4];
                if (bias[ph]) {
                    float4 b0 = *(const float4*)&bias[ph][cg];
                    float4 b1 = *(const float4*)&bias[ph][cg + 4];
                    st0.x += b0.x; st0.y += b0.y; st0.z += b0.z; st0.w += b0.w;
                    st1.x += b1.x; st1.y += b1.y; st1.z += b1.z; st1.w += b1.w;
                }
                *(float4*)&O[(size_t)n * H + cg]     = st0;
                *(float4*)&O[(size_t)n * H + cg + 4] = st1;
            }
        }
    }
}

// ---- k_edge (R11 config, 2 CTA/SM): m=ReLU(A[src]+ef@We2+C[dst]);
//      out2=m+ef (ef = hi+lo smem images); scatter mean ----
__global__ __launch_bounds__(NT, 2)
void k_edge(const float* __restrict__ ef,
            const int* __restrict__ src, const int* __restrict__ dst,
            float* __restrict__ out2) {
    extern __shared__ __align__(16) __half sm[];
    __half* sXhi = sm;
    __half* sXlo = sm + TILE_A;                  // lo kept ONLY for out2 = m + ef
    __half* sW   = sm + 2 * TILE_A;
    int*   s_src = (int*)(sm + 2 * TILE_A + TILE_W);
    int*   s_dst = s_src + BT;
    float* stage = (float*)(s_dst + BT);         // 2 x 16 x SSTRIDE
    int t = threadIdx.x, lane = t & 31, warp = t >> 5;

    fill_W(sW, 1, t, NT);                        // We2, resident for all tiles

    int rq = lane >> 2, cb = (warp >> 2) * 64 + (lane & 3) * 2;
    int wr = warp & 3;
    int lrow = t >> 4, cg = (t & 15) * 8;

    int tiles = NTILES - blockIdx.x * TPB;
    if (tiles > TPB) tiles = TPB;

    for (int tt = 0; tt < tiles; tt++) {
        int eb = (blockIdx.x * TPB + tt) * BT;
        if (t < BT) s_src[t] = src[eb + t];
        else if (t < 2 * BT) s_dst[t - BT] = dst[eb + t - BT];
        const float4* ef4 = (const float4*)(ef + (size_t)eb * H);
        for (int i = t; i < BT * 32; i += NT)
            split_store(sXhi, sXlo, (i >> 5) * STRIDE + (i & 31) * 4, ef4[i]);
        __syncthreads();

        // prefetch chunk 0 gathers (hidden under mainloop)
        int s_p = s_src[lrow], d_p = s_dst[lrow];
        float4 pa0 = *(const float4*)&g_A[(size_t)s_p * H + cg];
        float4 pa1 = *(const float4*)&g_A[(size_t)s_p * H + cg + 4];
        float4 pc0 = *(const float4*)&g_C[(size_t)d_p * H + cg];
        float4 pc1 = *(const float4*)&g_C[(size_t)d_p * H + cg + 4];

        float acc[8][4];
#pragma unroll
        for (int i = 0; i < 8; i++) acc[i][0] = acc[i][1] = acc[i][2] = acc[i][3] = 0.f;
        mma_core(sXhi, sW, lane, warp, acc);

#pragma unroll
        for (int c = 0; c < 4; c++) {
            float* stg = stage + (c & 1) * (16 * SSTRIDE);
            stage_chunk(stg, acc, c, wr, rq, cb);
            __syncthreads();                     // stage(c) ready

            int row = c * 16 + lrow;
            int d = d_p;
            if ((t & 15) == 0) atomicAdd(&g_cnt[d], 1.f);

            float4 st0 = *(float4*)&stg[lrow * SSTRIDE + cg];
            float4 st1 = *(float4*)&stg[lrow * SSTRIDE + cg + 4];
            float4 m0, m1;
            m0.x = fmaxf(st0.x + pa0.x + pc0.x, 0.f);
            m0.y = fmaxf(st0.y + pa0.y + pc0.y, 0.f);
            m0.z = fmaxf(st0.z + pa0.z + pc0.z, 0.f);
            m0.w = fmaxf(st0.w + pa0.w + pc0.w, 0.f);
            m1.x = fmaxf(st1.x + pa1.x + pc1.x, 0.f);
            m1.y = fmaxf(st1.y + pa1.y + pc1.y, 0.f);
            m1.z = fmaxf(st1.z + pa1.z + pc1.z, 0.f);
            m1.w = fmaxf(st1.w + pa1.w + pc1.w, 0.f);

            if (c < 3) {                         // next chunk's gathers
                int nrow = (c + 1) * 16 + lrow;
                s_p = s_src[nrow]; d_p = s_dst[nrow];
                pa0 = *(const float4*)&g_A[(size_t)s_p * H + cg];
                pa1 = *(const float4*)&g_A[(size_t)s_p * H + cg + 4];
                pc0 = *(const float4*)&g_C[(size_t)d_p * H + cg];
                pc1 = *(const float4*)&g_C[(size_t)d_p * H + cg + 4];
            }

            // ef reconstruct (hi+lo) from sX, row-major LDS.128
            uint4 uh = *(uint4*)&sXhi[row * STRIDE + cg];
            uint4 ul = *(uint4*)&sXlo[row * STRIDE + cg];
            const __half2* h2 = (const __half2*)&uh;
            const __half2* l2 = (const __half2*)&ul;
            float4 o0, o1;
            o0.x = (m0.x + __half2float(h2[0].x)) + __half2float(l2[0].x);
            o0.y = (m0.y + __half2float(h2[0].y)) + __half2float(l2[0].y);
            o0.z = (m0.z + __half2float(h2[1].x)) + __half2float(l2[1].x);
            o0.w = (m0.w + __half2float(h2[1].y)) + __half2float(l2[1].y);
            o1.x = (m1.x + __half2float(h2[2].x)) + __half2float(l2[2].x);
            o1.y = (m1.y + __half2float(h2[2].y)) + __half2float(l2[2].y);
            o1.z = (m1.z + __half2float(h2[3].x)) + __half2float(l2[3].x);
            o1.w = (m1.w + __half2float(h2[3].y)) + __half2float(l2[3].y);

            *(float4*)&out2[(size_t)(eb + row) * H + cg]     = o0;
            *(float4*)&out2[(size_t)(eb + row) * H + cg + 4] = o1;
            red_add_v4(&g_sum[(size_t)d * H + cg], m0);
            red_add_v4(&g_sum[(size_t)d * H + cg + 4], m1);
        }
        __syncthreads();                         // sX & stage free for next tile
    }
}

// ---- k_node_upd: out1 = ReLU(An + (sum/max(cnt,1))@Wn2) + nf (3 CTA/SM) ----
__global__ __launch_bounds__(NT, 3)
void k_node_upd(const float* __restrict__ nf, float* __restrict__ out1) {
    extern __shared__ __align__(16) __half sm[];
    __half* sX = sm;
    __half* sW = sm + TILE_A;
    float* stage = (float*)(sm + TILE_A + TILE_W);
    int t = threadIdx.x, lane = t & 31, warp = t >> 5;
    int nb = blockIdx.x * BT;

    for (int i = t; i < BT * 32; i += NT) {
        int n = nb + (i >> 5);
        float4 v = make_float4(0.f, 0.f, 0.f, 0.f);
        if (n < NNODE) {
            v = ((const float4*)g_sum)[(size_t)n * 32 + (i & 31)];
            float inv = 1.0f / fmaxf(g_cnt[n], 1.0f);
            v.x *= inv; v.y *= inv; v.z *= inv; v.w *= inv;
        }
        store_hi(sX, (i >> 5) * STRIDE + (i & 31) * 4, v);
    }
    fill_W(sW, 4, t, NT);                        // Wn2
    __syncthreads();

    float acc[8][4];
#pragma unroll
    for (int i = 0; i < 8; i++) acc[i][0] = acc[i][1] = acc[i][2] = acc[i][3] = 0.f;
    mma_core(sX, sW, lane, warp, acc);

    int rq = lane >> 2, cb = (warp >> 2) * 64 + (lane & 3) * 2;
    int wr = warp & 3;
    int lrow = t >> 4, cg = (t & 15) * 8;

#pragma unroll
    for (int c = 0; c < 4; c++) {
        float* stg = stage + (c & 1) * (16 * SSTRIDE);
        stage_chunk(stg, acc, c, wr, rq, cb);
        __syncthreads();
        int n = nb + c * 16 + lrow;
        if (n < NNODE) {
            float4 st0 = *(float4*)&stg[lrow * SSTRIDE + cg];
            float4 st1 = *(float4*)&stg[lrow * SSTRIDE + cg + 4];
            float4 an0 = *(const float4*)&g_An[(size_t)n * H + cg];
            float4 an1 = *(const float4*)&g_An[(size_t)n * H + cg + 4];
            float4 nv0 = *(const float4*)&nf[(size_t)n * H + cg];
            float4 nv1 = *(const float4*)&nf[(size_t)n * H + cg + 4];
            float4 o0, o1;
            o0.x = fmaxf(st0.x + an0.x, 0.f) + nv0.x;
            o0.y = fmaxf(st0.y + an0.y, 0.f) + nv0.y;
            o0.z = fmaxf(st0.z + an0.z, 0.f) + nv0.z;
            o0.w = fmaxf(st0.w + an0.w, 0.f) + nv0.w;
            o1.x = fmaxf(st1.x + an1.x, 0.f) + nv1.x;
            o1.y = fmaxf(st1.y + an1.y, 0.f) + nv1.y;
            o1.z = fmaxf(st1.z + an1.z, 0.f) + nv1.z;
            o1.w = fmaxf(st1.w + an1.w, 0.f) + nv1.w;
            *(float4*)&out1[(size_t)n * H + cg]     = o0;
            *(float4*)&out1[(size_t)n * H + cg + 4] = o1;
        }
    }
}

extern "C" void kernel_launch(void* const* d_in, const int* in_sizes, int n_in,
                              void* d_out, int out_size) {
    const float* nf  = (const float*)d_in[0];
    const float* ef  = (const float*)d_in[1];
    const int*   src = (const int*)d_in[2];
    const int*   dst = (const int*)d_in[3];
    const float* We  = (const float*)d_in[4];
    const float* be  = (const float*)d_in[5];
    const float* Wn  = (const float*)d_in[6];
    const float* bn  = (const float*)d_in[7];
    float* out1 = (float*)d_out;                    // [N,H]
    float* out2 = out1 + (size_t)NNODE * H;         // [E,H]

    const int smem_node = (TILE_A + TILE_W) * (int)sizeof(__half)
                        + 2 * 16 * SSTRIDE * (int)sizeof(float);              // 69632
    const int smem_edge = (2 * TILE_A + TILE_W) * (int)sizeof(__half)
                        + 2 * BT * (int)sizeof(int)
                        + 2 * 16 * SSTRIDE * (int)sizeof(float);              // 87552
    cudaFuncSetAttribute(k_node_pre, cudaFuncAttributeMaxDynamicSharedMemorySize, smem_node);
    cudaFuncSetAttribute(k_edge,     cudaFuncAttributeMaxDynamicSharedMemorySize, smem_edge);
    cudaFuncSetAttribute(k_node_upd, cudaFuncAttributeMaxDynamicSharedMemorySize, smem_node);

    k_prep<<<(5 * H * H + 255) / 256, 256>>>(We, Wn);
    k_node_pre<<<(NNODE + BT - 1) / BT, NT, smem_node>>>(nf, be, bn);
    k_edge<<<(NTILES + TPB - 1) / TPB, NT, smem_edge>>>(ef, src, dst, out2);
    k_node_upd<<<(NNODE + BT - 1) / BT, NT, smem_node>>>(nf, out1);
}

// round 15
// speedup vs baseline: 1.1425x; 1.0240x over previous
#include <cuda_runtime.h>
#include <cuda_fp16.h>
#include <cstdint>

// GCNLayer_EdgeCat on GB300 — R15: all kernels at 3 CTAs/SM.
//   k_edge drops the ef-lo smem image entirely: out2 = m + ef_hi(fp16).
//   Error ledger: m carries 1.7e-4 (calibrated); ef-hi rounding adds ~1.4e-4
//   RMS in quadrature => ~2-3e-4 total, gate 1e-3. Buys smem_edge=70.1KB ->
//   3 CTAs/SM (the regime that measurably sped nodes up 15%), with no global
//   ef re-read (R12 failure) and no register residuals (R13 failure).
//   We=[We1;We2;We3], Wn=[Wn1;Wn2]:
//     A=nf@We1+be, C=nf@We3, An=nf@Wn1+bn        (k_node_pre)
//     m=ReLU(A[src]+ef@We2+C[dst]); out2=m+ef    (k_edge, scatter mean)
//     out1=ReLU(An+mean@Wn2)+nf                  (k_node_upd)

#define H        128
#define NNODE    50000
#define NEDGE    800000
#define BT       64           // rows per tile
#define NT       256          // 8 warps: warp = 16 rows x 64 cols
#define TPB      8            // edge tiles per block (last block: tail guard)
#define NTILES   (NEDGE / BT) // 12500
#define STRIDE   136          // fp16 row stride (272B, LDSM conflict-free)
#define SSTRIDE  136          // f32 stage stride
#define TILE_A   (BT * STRIDE)
#define TILE_W   (H * STRIDE)

__device__ float g_A  [(size_t)NNODE * H];
__device__ float g_C  [(size_t)NNODE * H];
__device__ float g_An [(size_t)NNODE * H];
__device__ float g_sum[(size_t)NNODE * H];
__device__ float g_cnt[NNODE];
// 5 weights (We1,We2,We3,Wn1,Wn2): [k][n] row-major fp16.
__device__ __half g_Wimg[5 * H * H];

// ---------- PTX helpers ----------
__device__ __forceinline__ uint32_t smem_u32(const void* p) {
    return (uint32_t)__cvta_generic_to_shared(p);
}
__device__ __forceinline__ void ldsm_x4(uint32_t a[4], uint32_t addr) {
    asm volatile("ldmatrix.sync.aligned.m8n8.x4.shared.b16 {%0,%1,%2,%3}, [%4];"
                 : "=r"(a[0]), "=r"(a[1]), "=r"(a[2]), "=r"(a[3]) : "r"(addr));
}
__device__ __forceinline__ void ldsm_x4_t(uint32_t b[4], uint32_t addr) {
    asm volatile("ldmatrix.sync.aligned.m8n8.x4.trans.shared.b16 {%0,%1,%2,%3}, [%4];"
                 : "=r"(b[0]), "=r"(b[1]), "=r"(b[2]), "=r"(b[3]) : "r"(addr));
}
__device__ __forceinline__ void mma16816(float c[4], const uint32_t a[4], const uint32_t b[2]) {
    asm volatile("mma.sync.aligned.m16n8k16.row.col.f32.f16.f16.f32 "
                 "{%0,%1,%2,%3}, {%4,%5,%6,%7}, {%8,%9}, {%0,%1,%2,%3};"
                 : "+f"(c[0]), "+f"(c[1]), "+f"(c[2]), "+f"(c[3])
                 : "r"(a[0]), "r"(a[1]), "r"(a[2]), "r"(a[3]), "r"(b[0]), "r"(b[1]));
}
__device__ __forceinline__ void red_add_v4(float* p, float4 v) {
    asm volatile("red.global.add.v4.f32 [%0], {%1, %2, %3, %4};"
                 :: "l"(p), "f"(v.x), "f"(v.y), "f"(v.z), "f"(v.w) : "memory");
}

// Store a float4 as 4 fp16 at element offset off.
__device__ __forceinline__ void store_hi(__half* hi, int off, float4 v) {
    *(__half2*)(hi + off)     = __half2{__float2half_rn(v.x), __float2half_rn(v.y)};
    *(__half2*)(hi + off + 2) = __half2{__float2half_rn(v.z), __float2half_rn(v.w)};
}

// 8-warp core: warp tile 16 rows x 64 cols, single-term fp16 (64 MMAs).
// acc[nt][0..1]: row (warp&3)*16 + lane>>2,   col (warp>>2)*64 + nt*8 + (lane&3)*2
// acc[nt][2..3]: row +8, same cols.
__device__ __forceinline__ void mma_core(const __half* sX, const __half* sW,
                                         int lane, int warp, float acc[8][4]) {
    uint32_t x = smem_u32(sX), w = smem_u32(sW);
    int r0 = (warp & 3) * 16, c0 = (warp >> 2) * 64;
    uint32_t aoff = (uint32_t)((r0 + (lane & 15)) * STRIDE + ((lane >> 4) << 3)) * 2;
    uint32_t boff = (uint32_t)((lane & 15) * STRIDE + c0 + ((lane >> 4) << 3)) * 2;
#pragma unroll
    for (int k0 = 0; k0 < H; k0 += 16) {
        uint32_t a[4];
        ldsm_x4(a, x + aoff + k0 * 2);
#pragma unroll
        for (int ntp = 0; ntp < 4; ntp++) {
            uint32_t b[4];
            ldsm_x4_t(b, w + boff + (uint32_t)(k0 * STRIDE + ntp * 16) * 2);
            mma16816(acc[2 * ntp],     a, b + 0);
            mma16816(acc[2 * ntp + 1], a, b + 2);
        }
    }
}

// Stage one 16-row chunk of acc into smem (warps wr==c and wr==c+4 write).
__device__ __forceinline__ void stage_chunk(float* stg, const float acc[8][4],
                                            int c, int wr, int rq, int cb) {
    if (wr == c) {
#pragma unroll
        for (int nt = 0; nt < 8; nt++) {
            int col = cb + nt * 8;
            *(float2*)&stg[rq * SSTRIDE + col] = make_float2(acc[nt][0], acc[nt][1]);
            *(float2*)&stg[(rq + 8) * SSTRIDE + col] = make_float2(acc[nt][2], acc[nt][3]);
        }
    }
}

// Copy a prepped W image ([k][n] 128x128 fp16) into padded smem.
__device__ __forceinline__ void fill_W(__half* sW, int wsel, int t, int nthr) {
    const uint4* w4 = (const uint4*)(g_Wimg + (size_t)wsel * H * H);
    for (int i = t; i < H * H / 8; i += nthr) {       // 2048 uint4
        int row = i >> 4, c8 = (i & 15) * 8;
        *(uint4*)(sW + row * STRIDE + c8) = w4[i];
    }
}

// ---- k_prep: weights -> fp16 [k][n] images (once) ----
__global__ void k_prep(const float* __restrict__ We, const float* __restrict__ Wn) {
    int idx = blockIdx.x * blockDim.x + threadIdx.x;
    if (idx >= 5 * H * H) return;
    int w = idx / (H * H), r = idx % (H * H);
    const float* src = (w < 3) ? (We + w * H * H) : (Wn + (w - 3) * H * H);
    g_Wimg[(size_t)w * H * H + r] = __float2half_rn(src[r]);
}

// ---- k_node_pre: zero sums; A=nf@We1+be, C=nf@We3, An=nf@Wn1+bn (3 CTA/SM) ----
__global__ __launch_bounds__(NT, 3)
void k_node_pre(const float* __restrict__ nf,
                const float* __restrict__ be, const float* __restrict__ bn) {
    extern __shared__ __align__(16) __half sm[];
    __half* sX = sm;
    __half* sW = sm + TILE_A;
    float* stage = (float*)(sm + TILE_A + TILE_W);   // 2 x 16 x SSTRIDE
    int t = threadIdx.x, lane = t & 31, warp = t >> 5;
    int nb = blockIdx.x * BT;

    for (int i = t; i < BT * 32; i += NT) {
        int n = nb + (i >> 5);
        if (n < NNODE) ((float4*)g_sum)[(size_t)n * 32 + (i & 31)] = make_float4(0.f, 0.f, 0.f, 0.f);
    }
    if (t < BT && nb + t < NNODE) g_cnt[nb + t] = 0.f;

    for (int i = t; i < BT * 32; i += NT) {
        int n = nb + (i >> 5);
        float4 v = make_float4(0.f, 0.f, 0.f, 0.f);
        if (n < NNODE) v = ((const float4*)nf)[(size_t)n * 32 + (i & 31)];
        store_hi(sX, (i >> 5) * STRIDE + (i & 31) * 4, v);
    }

    const int    wsel[3] = {0, 2, 3};
    float*       Od[3]   = {g_A, g_C, g_An};
    const float* bias[3] = {be, (const float*)0, bn};

    int rq = lane >> 2, cb = (warp >> 2) * 64 + (lane & 3) * 2;
    int wr = warp & 3;
    int lrow = t >> 4, cg = (t & 15) * 8;        // epilogue ownership

    for (int ph = 0; ph < 3; ph++) {
        __syncthreads();                         // prev phase fully consumed
        fill_W(sW, wsel[ph], t, NT);
        __syncthreads();

        float acc[8][4];
#pragma unroll
        for (int i = 0; i < 8; i++) acc[i][0] = acc[i][1] = acc[i][2] = acc[i][3] = 0.f;
        mma_core(sX, sW, lane, warp, acc);

        float* O = Od[ph];
#pragma unroll
        for (int c = 0; c < 4; c++) {
            float* stg = stage + (c & 1) * (16 * SSTRIDE);
            stage_chunk(stg, acc, c, wr, rq, cb);
            __syncthreads();                     // stage(c) ready
            int n = nb + c * 16 + lrow;
            if (n < NNODE) {
                float4 st0 = *(float4*)&stg[lrow * SSTRIDE + cg];
                float4 st1 = *(float4*)&stg[lrow * SSTRIDE + cg + 4];
                if (bias[ph]) {
                    float4 b0 = *(const float4*)&bias[ph][cg];
                    float4 b1 = *(const float4*)&bias[ph][cg + 4];
                    st0.x += b0.x; st0.y += b0.y; st0.z += b0.z; st0.w += b0.w;
                    st1.x += b1.x; st1.y += b1.y; st1.z += b1.z; st1.w += b1.w;
                }
                *(float4*)&O[(size_t)n * H + cg]     = st0;
                *(float4*)&O[(size_t)n * H + cg + 4] = st1;
            }
        }
    }
}

// ---- k_edge (3 CTA/SM): m=ReLU(A[src]+ef@We2+C[dst]);
//      out2 = m + ef_hi (fp16 ef from sX); scatter mean ----
__global__ __launch_bounds__(NT, 3)
void k_edge(const float* __restrict__ ef,
            const int* __restrict__ src, const int* __restrict__ dst,
            float* __restrict__ out2) {
    extern __shared__ __align__(16) __half sm[];
    __half* sX   = sm;
    __half* sW   = sm + TILE_A;
    int*   s_src = (int*)(sm + TILE_A + TILE_W);
    int*   s_dst = s_src + BT;
    float* stage = (float*)(s_dst + BT);         // 2 x 16 x SSTRIDE
    int t = threadIdx.x, lane = t & 31, warp = t >> 5;

    fill_W(sW, 1, t, NT);                        // We2, resident for all tiles

    int rq = lane >> 2, cb = (warp >> 2) * 64 + (lane & 3) * 2;
    int wr = warp & 3;
    int lrow = t >> 4, cg = (t & 15) * 8;

    int tiles = NTILES - blockIdx.x * TPB;
    if (tiles > TPB) tiles = TPB;

    for (int tt = 0; tt < tiles; tt++) {
        int eb = (blockIdx.x * TPB + tt) * BT;
        if (t < BT) s_src[t] = src[eb + t];
        else if (t < 2 * BT) s_dst[t - BT] = dst[eb + t - BT];
        const float4* ef4 = (const float4*)(ef + (size_t)eb * H);
        for (int i = t; i < BT * 32; i += NT)
            store_hi(sX, (i >> 5) * STRIDE + (i & 31) * 4, ef4[i]);
        __syncthreads();

        // prefetch chunk 0 gathers (hidden under mainloop)
        int s_p = s_src[lrow], d_p = s_dst[lrow];
        float4 pa0 = *(const float4*)&g_A[(size_t)s_p * H + cg];
        float4 pa1 = *(const float4*)&g_A[(size_t)s_p * H + cg + 4];
        float4 pc0 = *(const float4*)&g_C[(size_t)d_p * H + cg];
        float4 pc1 = *(const float4*)&g_C[(size_t)d_p * H + cg + 4];

        float acc[8][4];
#pragma unroll
        for (int i = 0; i < 8; i++) acc[i][0] = acc[i][1] = acc[i][2] = acc[i][3] = 0.f;
        mma_core(sX, sW, lane, warp, acc);

#pragma unroll
        for (int c = 0; c < 4; c++) {
            float* stg = stage + (c & 1) * (16 * SSTRIDE);
            stage_chunk(stg, acc, c, wr, rq, cb);
            __syncthreads();                     // stage(c) ready

            int row = c * 16 + lrow;
            int d = d_p;
            if ((t & 15) == 0) atomicAdd(&g_cnt[d], 1.f);

            float4 st0 = *(float4*)&stg[lrow * SSTRIDE + cg];
            float4 st1 = *(float4*)&stg[lrow * SSTRIDE + cg + 4];
            float4 m0, m1;
            m0.x = fmaxf(st0.x + pa0.x + pc0.x, 0.f);
            m0.y = fmaxf(st0.y + pa0.y + pc0.y, 0.f);
            m0.z = fmaxf(st0.z + pa0.z + pc0.z, 0.f);
            m0.w = fmaxf(st0.w + pa0.w + pc0.w, 0.f);
            m1.x = fmaxf(st1.x + pa1.x + pc1.x, 0.f);
            m1.y = fmaxf(st1.y + pa1.y + pc1.y, 0.f);
            m1.z = fmaxf(st1.z + pa1.z + pc1.z, 0.f);
            m1.w = fmaxf(st1.w + pa1.w + pc1.w, 0.f);

            if (c < 3) {                         // next chunk's gathers
                int nrow = (c + 1) * 16 + lrow;
                s_p = s_src[nrow]; d_p = s_dst[nrow];
                pa0 = *(const float4*)&g_A[(size_t)s_p * H + cg];
                pa1 = *(const float4*)&g_A[(size_t)s_p * H + cg + 4];
                pc0 = *(const float4*)&g_C[(size_t)d_p * H + cg];
                pc1 = *(const float4*)&g_C[(size_t)d_p * H + cg + 4];
            }

            // ef_hi from sX (fp16; error absorbed by the calibrated budget)
            uint4 uh = *(uint4*)&sX[row * STRIDE + cg];
            const __half2* h2 = (const __half2*)&uh;
            float4 o0, o1;
            o0.x = m0.x + __half2float(h2[0].x);
            o0.y = m0.y + __half2float(h2[0].y);
            o0.z = m0.z + __half2float(h2[1].x);
            o0.w = m0.w + __half2float(h2[1].y);
            o1.x = m1.x + __half2float(h2[2].x);
            o1.y = m1.y + __half2float(h2[2].y);
            o1.z = m1.z + __half2float(h2[3].x);
            o1.w = m1.w + __half2float(h2[3].y);

            *(float4*)&out2[(size_t)(eb + row) * H + cg]     = o0;
            *(float4*)&out2[(size_t)(eb + row) * H + cg + 4] = o1;
            red_add_v4(&g_sum[(size_t)d * H + cg], m0);
            red_add_v4(&g_sum[(size_t)d * H + cg + 4], m1);
        }
        __syncthreads();                         // sX & stage free for next tile
    }
}

// ---- k_node_upd: out1 = ReLU(An + (sum/max(cnt,1))@Wn2) + nf (3 CTA/SM) ----
__global__ __launch_bounds__(NT, 3)
void k_node_upd(const float* __restrict__ nf, float* __restrict__ out1) {
    extern __shared__ __align__(16) __half sm[];
    __half* sX = sm;
    __half* sW = sm + TILE_A;
    float* stage = (float*)(sm + TILE_A + TILE_W);
    int t = threadIdx.x, lane = t & 31, warp = t >> 5;
    int nb = blockIdx.x * BT;

    for (int i = t; i < BT * 32; i += NT) {
        int n = nb + (i >> 5);
        float4 v = make_float4(0.f, 0.f, 0.f, 0.f);
        if (n < NNODE) {
            v = ((const float4*)g_sum)[(size_t)n * 32 + (i & 31)];
            float inv = 1.0f / fmaxf(g_cnt[n], 1.0f);
            v.x *= inv; v.y *= inv; v.z *= inv; v.w *= inv;
        }
        store_hi(sX, (i >> 5) * STRIDE + (i & 31) * 4, v);
    }
    fill_W(sW, 4, t, NT);                        // Wn2
    __syncthreads();

    float acc[8][4];
#pragma unroll
    for (int i = 0; i < 8; i++) acc[i][0] = acc[i][1] = acc[i][2] = acc[i][3] = 0.f;
    mma_core(sX, sW, lane, warp, acc);

    int rq = lane >> 2, cb = (warp >> 2) * 64 + (lane & 3) * 2;
    int wr = warp & 3;
    int lrow = t >> 4, cg = (t & 15) * 8;

#pragma unroll
    for (int c = 0; c < 4; c++) {
        float* stg = stage + (c & 1) * (16 * SSTRIDE);
        stage_chunk(stg, acc, c, wr, rq, cb);
        __syncthreads();
        int n = nb + c * 16 + lrow;
        if (n < NNODE) {
            float4 st0 = *(float4*)&stg[lrow * SSTRIDE + cg];
            float4 st1 = *(float4*)&stg[lrow * SSTRIDE + cg + 4];
            float4 an0 = *(const float4*)&g_An[(size_t)n * H + cg];
            float4 an1 = *(const float4*)&g_An[(size_t)n * H + cg + 4];
            float4 nv0 = *(const float4*)&nf[(size_t)n * H + cg];
            float4 nv1 = *(const float4*)&nf[(size_t)n * H + cg + 4];
            float4 o0, o1;
            o0.x = fmaxf(st0.x + an0.x, 0.f) + nv0.x;
            o0.y = fmaxf(st0.y + an0.y, 0.f) + nv0.y;
            o0.z = fmaxf(st0.z + an0.z, 0.f) + nv0.z;
            o0.w = fmaxf(st0.w + an0.w, 0.f) + nv0.w;
            o1.x = fmaxf(st1.x + an1.x, 0.f) + nv1.x;
            o1.y = fmaxf(st1.y + an1.y, 0.f) + nv1.y;
            o1.z = fmaxf(st1.z + an1.z, 0.f) + nv1.z;
            o1.w = fmaxf(st1.w + an1.w, 0.f) + nv1.w;
            *(float4*)&out1[(size_t)n * H + cg]     = o0;
            *(float4*)&out1[(size_t)n * H + cg + 4] = o1;
        }
    }
}

extern "C" void kernel_launch(void* const* d_in, const int* in_sizes, int n_in,
                              void* d_out, int out_size) {
    const float* nf  = (const float*)d_in[0];
    const float* ef  = (const float*)d_in[1];
    const int*   src = (const int*)d_in[2];
    const int*   dst = (const int*)d_in[3];
    const float* We  = (const float*)d_in[4];
    const float* be  = (const float*)d_in[5];
    const float* Wn  = (const float*)d_in[6];
    const float* bn  = (const float*)d_in[7];
    float* out1 = (float*)d_out;                    // [N,H]
    float* out2 = out1 + (size_t)NNODE * H;         // [E,H]

    const int smem_node = (TILE_A + TILE_W) * (int)sizeof(__half)
                        + 2 * 16 * SSTRIDE * (int)sizeof(float);              // 69632
    const int smem_edge = (TILE_A + TILE_W) * (int)sizeof(__half)
                        + 2 * BT * (int)sizeof(int)
                        + 2 * 16 * SSTRIDE * (int)sizeof(float);              // 70144
    cudaFuncSetAttribute(k_node_pre, cudaFuncAttributeMaxDynamicSharedMemorySize, smem_node);
    cudaFuncSetAttribute(k_edge,     cudaFuncAttributeMaxDynamicSharedMemorySize, smem_edge);
    cudaFuncSetAttribute(k_node_upd, cudaFuncAttributeMaxDynamicSharedMemorySize, smem_node);

    k_prep<<<(5 * H * H + 255) / 256, 256>>>(We, Wn);
    k_node_pre<<<(NNODE + BT - 1) / BT, NT, smem_node>>>(nf, be, bn);
    k_edge<<<(NTILES + TPB - 1) / TPB, NT, smem_edge>>>(ef, src, dst, out2);
    k_node_upd<<<(NNODE + BT - 1) / BT, NT, smem_node>>>(nf, out1);
}

// round 16
// speedup vs baseline: 1.1892x; 1.0409x over previous
#include <cuda_runtime.h>
#include <cuda_fp16.h>
#include <cstdint>

// GCNLayer_EdgeCat on GB300 — R16: persistent k_edge (grid = SMs x occupancy,
// grid-strided tiles) kills wave quantization (3.52 -> 1 wave; worst slot
// 32 -> 29 tile-times) and cuts We2 refills 1563 -> ~444.
//   We=[We1;We2;We3], Wn=[Wn1;Wn2]:
//     A=nf@We1+be, C=nf@We3, An=nf@Wn1+bn        (k_node_pre)
//     m=ReLU(A[src]+ef@We2+C[dst]); out2=m+ef_hi (k_edge, scatter mean)
//     out1=ReLU(An+mean@Wn2)+nf                  (k_node_upd)
//   GEMMs: single fp16 (calibrated rel_err 2.4e-4, gate 1e-3). 3 CTAs/SM.

#define H        128
#define NNODE    50000
#define NEDGE    800000
#define BT       64           // rows per tile
#define NT       256          // 8 warps: warp = 16 rows x 64 cols
#define NTILES   (NEDGE / BT) // 12500
#define STRIDE   136          // fp16 row stride (272B, LDSM conflict-free)
#define SSTRIDE  136          // f32 stage stride
#define TILE_A   (BT * STRIDE)
#define TILE_W   (H * STRIDE)

__device__ float g_A  [(size_t)NNODE * H];
__device__ float g_C  [(size_t)NNODE * H];
__device__ float g_An [(size_t)NNODE * H];
__device__ float g_sum[(size_t)NNODE * H];
__device__ float g_cnt[NNODE];
// 5 weights (We1,We2,We3,Wn1,Wn2): [k][n] row-major fp16.
__device__ __half g_Wimg[5 * H * H];

// ---------- PTX helpers ----------
__device__ __forceinline__ uint32_t smem_u32(const void* p) {
    return (uint32_t)__cvta_generic_to_shared(p);
}
__device__ __forceinline__ void ldsm_x4(uint32_t a[4], uint32_t addr) {
    asm volatile("ldmatrix.sync.aligned.m8n8.x4.shared.b16 {%0,%1,%2,%3}, [%4];"
                 : "=r"(a[0]), "=r"(a[1]), "=r"(a[2]), "=r"(a[3]) : "r"(addr));
}
__device__ __forceinline__ void ldsm_x4_t(uint32_t b[4], uint32_t addr) {
    asm volatile("ldmatrix.sync.aligned.m8n8.x4.trans.shared.b16 {%0,%1,%2,%3}, [%4];"
                 : "=r"(b[0]), "=r"(b[1]), "=r"(b[2]), "=r"(b[3]) : "r"(addr));
}
__device__ __forceinline__ void mma16816(float c[4], const uint32_t a[4], const uint32_t b[2]) {
    asm volatile("mma.sync.aligned.m16n8k16.row.col.f32.f16.f16.f32 "
                 "{%0,%1,%2,%3}, {%4,%5,%6,%7}, {%8,%9}, {%0,%1,%2,%3};"
                 : "+f"(c[0]), "+f"(c[1]), "+f"(c[2]), "+f"(c[3])
                 : "r"(a[0]), "r"(a[1]), "r"(a[2]), "r"(a[3]), "r"(b[0]), "r"(b[1]));
}
__device__ __forceinline__ void red_add_v4(float* p, float4 v) {
    asm volatile("red.global.add.v4.f32 [%0], {%1, %2, %3, %4};"
                 :: "l"(p), "f"(v.x), "f"(v.y), "f"(v.z), "f"(v.w) : "memory");
}

// Store a float4 as 4 fp16 at element offset off.
__device__ __forceinline__ void store_hi(__half* hi, int off, float4 v) {
    *(__half2*)(hi + off)     = __half2{__float2half_rn(v.x), __float2half_rn(v.y)};
    *(__half2*)(hi + off + 2) = __half2{__float2half_rn(v.z), __float2half_rn(v.w)};
}

// 8-warp core: warp tile 16 rows x 64 cols, single-term fp16 (64 MMAs).
__device__ __forceinline__ void mma_core(const __half* sX, const __half* sW,
                                         int lane, int warp, float acc[8][4]) {
    uint32_t x = smem_u32(sX), w = smem_u32(sW);
    int r0 = (warp & 3) * 16, c0 = (warp >> 2) * 64;
    uint32_t aoff = (uint32_t)((r0 + (lane & 15)) * STRIDE + ((lane >> 4) << 3)) * 2;
    uint32_t boff = (uint32_t)((lane & 15) * STRIDE + c0 + ((lane >> 4) << 3)) * 2;
#pragma unroll
    for (int k0 = 0; k0 < H; k0 += 16) {
        uint32_t a[4];
        ldsm_x4(a, x + aoff + k0 * 2);
#pragma unroll
        for (int ntp = 0; ntp < 4; ntp++) {
            uint32_t b[4];
            ldsm_x4_t(b, w + boff + (uint32_t)(k0 * STRIDE + ntp * 16) * 2);
            mma16816(acc[2 * ntp],     a, b + 0);
            mma16816(acc[2 * ntp + 1], a, b + 2);
        }
    }
}

// Stage one 16-row chunk of acc into smem (warps wr==c and wr==c+4 write).
__device__ __forceinline__ void stage_chunk(float* stg, const float acc[8][4],
                                            int c, int wr, int rq, int cb) {
    if (wr == c) {
#pragma unroll
        for (int nt = 0; nt < 8; nt++) {
            int col = cb + nt * 8;
            *(float2*)&stg[rq * SSTRIDE + col] = make_float2(acc[nt][0], acc[nt][1]);
            *(float2*)&stg[(rq + 8) * SSTRIDE + col] = make_float2(acc[nt][2], acc[nt][3]);
        }
    }
}

// Copy a prepped W image ([k][n] 128x128 fp16) into padded smem.
__device__ __forceinline__ void fill_W(__half* sW, int wsel, int t, int nthr) {
    const uint4* w4 = (const uint4*)(g_Wimg + (size_t)wsel * H * H);
    for (int i = t; i < H * H / 8; i += nthr) {       // 2048 uint4
        int row = i >> 4, c8 = (i & 15) * 8;
        *(uint4*)(sW + row * STRIDE + c8) = w4[i];
    }
}

// ---- k_prep: weights -> fp16 [k][n] images (once) ----
__global__ void k_prep(const float* __restrict__ We, const float* __restrict__ Wn) {
    int idx = blockIdx.x * blockDim.x + threadIdx.x;
    if (idx >= 5 * H * H) return;
    int w = idx / (H * H), r = idx % (H * H);
    const float* src = (w < 3) ? (We + w * H * H) : (Wn + (w - 3) * H * H);
    g_Wimg[(size_t)w * H * H + r] = __float2half_rn(src[r]);
}

// ---- k_node_pre: zero sums; A=nf@We1+be, C=nf@We3, An=nf@Wn1+bn (3 CTA/SM) ----
__global__ __launch_bounds__(NT, 3)
void k_node_pre(const float* __restrict__ nf,
                const float* __restrict__ be, const float* __restrict__ bn) {
    extern __shared__ __align__(16) __half sm[];
    __half* sX = sm;
    __half* sW = sm + TILE_A;
    float* stage = (float*)(sm + TILE_A + TILE_W);   // 2 x 16 x SSTRIDE
    int t = threadIdx.x, lane = t & 31, warp = t >> 5;
    int nb = blockIdx.x * BT;

    for (int i = t; i < BT * 32; i += NT) {
        int n = nb + (i >> 5);
        if (n < NNODE) ((float4*)g_sum)[(size_t)n * 32 + (i & 31)] = make_float4(0.f, 0.f, 0.f, 0.f);
    }
    if (t < BT && nb + t < NNODE) g_cnt[nb + t] = 0.f;

    for (int i = t; i < BT * 32; i += NT) {
        int n = nb + (i >> 5);
        float4 v = make_float4(0.f, 0.f, 0.f, 0.f);
        if (n < NNODE) v = ((const float4*)nf)[(size_t)n * 32 + (i & 31)];
        store_hi(sX, (i >> 5) * STRIDE + (i & 31) * 4, v);
    }

    const int    wsel[3] = {0, 2, 3};
    float*       Od[3]   = {g_A, g_C, g_An};
    const float* bias[3] = {be, (const float*)0, bn};

    int rq = lane >> 2, cb = (warp >> 2) * 64 + (lane & 3) * 2;
    int wr = warp & 3;
    int lrow = t >> 4, cg = (t & 15) * 8;        // epilogue ownership

    for (int ph = 0; ph < 3; ph++) {
        __syncthreads();                         // prev phase fully consumed
        fill_W(sW, wsel[ph], t, NT);
        __syncthreads();

        float acc[8][4];
#pragma unroll
        for (int i = 0; i < 8; i++) acc[i][0] = acc[i][1] = acc[i][2] = acc[i][3] = 0.f;
        mma_core(sX, sW, lane, warp, acc);

        float* O = Od[ph];
#pragma unroll
        for (int c = 0; c < 4; c++) {
            float* stg = stage + (c & 1) * (16 * SSTRIDE);
            stage_chunk(stg, acc, c, wr, rq, cb);
            __syncthreads();                     // stage(c) ready
            int n = nb + c * 16 + lrow;
            if (n < NNODE) {
                float4 st0 = *(float4*)&stg[lrow * SSTRIDE + cg];
                float4 st1 = *(float4*)&stg[lrow * SSTRIDE + cg + 4];
                if (bias[ph]) {
                    float4 b0 = *(const float4*)&bias[ph][cg];
                    float4 b1 = *(const float4*)&bias[ph][cg + 4];
                    st0.x += b0.x; st0.y += b0.y; st0.z += b0.z; st0.w += b0.w;
                    st1.x += b1.x; st1.y += b1.y; st1.z += b1.z; st1.w += b1.w;
                }
                *(float4*)&O[(size_t)n * H + cg]     = st0;
                *(float4*)&O[(size_t)n * H + cg + 4] = st1;
            }
        }
    }
}

// ---- k_edge (persistent, 3 CTA/SM): grid-strided tiles, W filled once ----
__global__ __launch_bounds__(NT, 3)
void k_edge(const float* __restrict__ ef,
            const int* __restrict__ src, const int* __restrict__ dst,
            float* __restrict__ out2) {
    extern __shared__ __align__(16) __half sm[];
    __half* sX   = sm;
    __half* sW   = sm + TILE_A;
    int*   s_src = (int*)(sm + TILE_A + TILE_W);
    int*   s_dst = s_src + BT;
    float* stage = (float*)(s_dst + BT);         // 2 x 16 x SSTRIDE
    int t = threadIdx.x, lane = t & 31, warp = t >> 5;

    fill_W(sW, 1, t, NT);                        // We2, resident for ALL tiles

    int rq = lane >> 2, cb = (warp >> 2) * 64 + (lane & 3) * 2;
    int wr = warp & 3;
    int lrow = t >> 4, cg = (t & 15) * 8;

    for (int tile = blockIdx.x; tile < NTILES; tile += gridDim.x) {
        int eb = tile * BT;
        if (t < BT) s_src[t] = src[eb + t];
        else if (t < 2 * BT) s_dst[t - BT] = dst[eb + t - BT];
        const float4* ef4 = (const float4*)(ef + (size_t)eb * H);
        for (int i = t; i < BT * 32; i += NT)
            store_hi(sX, (i >> 5) * STRIDE + (i & 31) * 4, ef4[i]);
        __syncthreads();                         // sX (and first-iter sW) ready

        // prefetch chunk 0 gathers (hidden under mainloop)
        int s_p = s_src[lrow], d_p = s_dst[lrow];
        float4 pa0 = *(const float4*)&g_A[(size_t)s_p * H + cg];
        float4 pa1 = *(const float4*)&g_A[(size_t)s_p * H + cg + 4];
        float4 pc0 = *(const float4*)&g_C[(size_t)d_p * H + cg];
        float4 pc1 = *(const float4*)&g_C[(size_t)d_p * H + cg + 4];

        float acc[8][4];
#pragma unroll
        for (int i = 0; i < 8; i++) acc[i][0] = acc[i][1] = acc[i][2] = acc[i][3] = 0.f;
        mma_core(sX, sW, lane, warp, acc);

#pragma unroll
        for (int c = 0; c < 4; c++) {
            float* stg = stage + (c & 1) * (16 * SSTRIDE);
            stage_chunk(stg, acc, c, wr, rq, cb);
            __syncthreads();                     // stage(c) ready

            int row = c * 16 + lrow;
            int d = d_p;
            if ((t & 15) == 0) atomicAdd(&g_cnt[d], 1.f);

            float4 st0 = *(float4*)&stg[lrow * SSTRIDE + cg];
            float4 st1 = *(float4*)&stg[lrow * SSTRIDE + cg + 4];
            float4 m0, m1;
            m0.x = fmaxf(st0.x + pa0.x + pc0.x, 0.f);
            m0.y = fmaxf(st0.y + pa0.y + pc0.y, 0.f);
            m0.z = fmaxf(st0.z + pa0.z + pc0.z, 0.f);
            m0.w = fmaxf(st0.w + pa0.w + pc0.w, 0.f);
            m1.x = fmaxf(st1.x + pa1.x + pc1.x, 0.f);
            m1.y = fmaxf(st1.y + pa1.y + pc1.y, 0.f);
            m1.z = fmaxf(st1.z + pa1.z + pc1.z, 0.f);
            m1.w = fmaxf(st1.w + pa1.w + pc1.w, 0.f);

            if (c < 3) {                         // next chunk's gathers
                int nrow = (c + 1) * 16 + lrow;
                s_p = s_src[nrow]; d_p = s_dst[nrow];
                pa0 = *(const float4*)&g_A[(size_t)s_p * H + cg];
                pa1 = *(const float4*)&g_A[(size_t)s_p * H + cg + 4];
                pc0 = *(const float4*)&g_C[(size_t)d_p * H + cg];
                pc1 = *(const float4*)&g_C[(size_t)d_p * H + cg + 4];
            }

            // ef_hi from sX (fp16; error absorbed by the calibrated budget)
            uint4 uh = *(uint4*)&sX[row * STRIDE + cg];
            const __half2* h2 = (const __half2*)&uh;
            float4 o0, o1;
            o0.x = m0.x + __half2float(h2[0].x);
            o0.y = m0.y + __half2float(h2[0].y);
            o0.z = m0.z + __half2float(h2[1].x);
            o0.w = m0.w + __half2float(h2[1].y);
            o1.x = m1.x + __half2float(h2[2].x);
            o1.y = m1.y + __half2float(h2[2].y);
            o1.z = m1.z + __half2float(h2[3].x);
            o1.w = m1.w + __half2float(h2[3].y);

            *(float4*)&out2[(size_t)(eb + row) * H + cg]     = o0;
            *(float4*)&out2[(size_t)(eb + row) * H + cg + 4] = o1;
            red_add_v4(&g_sum[(size_t)d * H + cg], m0);
            red_add_v4(&g_sum[(size_t)d * H + cg + 4], m1);
        }
        __syncthreads();                         // sX & stage free for next tile
    }
}

// ---- k_node_upd: out1 = ReLU(An + (sum/max(cnt,1))@Wn2) + nf (3 CTA/SM) ----
__global__ __launch_bounds__(NT, 3)
void k_node_upd(const float* __restrict__ nf, float* __restrict__ out1) {
    extern __shared__ __align__(16) __half sm[];
    __half* sX = sm;
    __half* sW = sm + TILE_A;
    float* stage = (float*)(sm + TILE_A + TILE_W);
    int t = threadIdx.x, lane = t & 31, warp = t >> 5;
    int nb = blockIdx.x * BT;

    for (int i = t; i < BT * 32; i += NT) {
        int n = nb + (i >> 5);
        float4 v = make_float4(0.f, 0.f, 0.f, 0.f);
        if (n < NNODE) {
            v = ((const float4*)g_sum)[(size_t)n * 32 + (i & 31)];
            float inv = 1.0f / fmaxf(g_cnt[n], 1.0f);
            v.x *= inv; v.y *= inv; v.z *= inv; v.w *= inv;
        }
        store_hi(sX, (i >> 5) * STRIDE + (i & 31) * 4, v);
    }
    fill_W(sW, 4, t, NT);                        // Wn2
    __syncthreads();

    float acc[8][4];
#pragma unroll
    for (int i = 0; i < 8; i++) acc[i][0] = acc[i][1] = acc[i][2] = acc[i][3] = 0.f;
    mma_core(sX, sW, lane, warp, acc);

    int rq = lane >> 2, cb = (warp >> 2) * 64 + (lane & 3) * 2;
    int wr = warp & 3;
    int lrow = t >> 4, cg = (t & 15) * 8;

#pragma unroll
    for (int c = 0; c < 4; c++) {
        float* stg = stage + (c & 1) * (16 * SSTRIDE);
        stage_chunk(stg, acc, c, wr, rq, cb);
        __syncthreads();
        int n = nb + c * 16 + lrow;
        if (n < NNODE) {
            float4 st0 = *(float4*)&stg[lrow * SSTRIDE + cg];
            float4 st1 = *(float4*)&stg[lrow * SSTRIDE + cg + 4];
            float4 an0 = *(const float4*)&g_An[(size_t)n * H + cg];
            float4 an1 = *(const float4*)&g_An[(size_t)n * H + cg + 4];
            float4 nv0 = *(const float4*)&nf[(size_t)n * H + cg];
            float4 nv1 = *(const float4*)&nf[(size_t)n * H + cg + 4];
            float4 o0, o1;
            o0.x = fmaxf(st0.x + an0.x, 0.f) + nv0.x;
            o0.y = fmaxf(st0.y + an0.y, 0.f) + nv0.y;
            o0.z = fmaxf(st0.z + an0.z, 0.f) + nv0.z;
            o0.w = fmaxf(st0.w + an0.w, 0.f) + nv0.w;
            o1.x = fmaxf(st1.x + an1.x, 0.f) + nv1.x;
            o1.y = fmaxf(st1.y + an1.y, 0.f) + nv1.y;
            o1.z = fmaxf(st1.z + an1.z, 0.f) + nv1.z;
            o1.w = fmaxf(st1.w + an1.w, 0.f) + nv1.w;
            *(float4*)&out1[(size_t)n * H + cg]     = o0;
            *(float4*)&out1[(size_t)n * H + cg + 4] = o1;
        }
    }
}

extern "C" void kernel_launch(void* const* d_in, const int* in_sizes, int n_in,
                              void* d_out, int out_size) {
    const float* nf  = (const float*)d_in[0];
    const float* ef  = (const float*)d_in[1];
    const int*   src = (const int*)d_in[2];
    const int*   dst = (const int*)d_in[3];
    const float* We  = (const float*)d_in[4];
    const float* be  = (const float*)d_in[5];
    const float* Wn  = (const float*)d_in[6];
    const float* bn  = (const float*)d_in[7];
    float* out1 = (float*)d_out;                    // [N,H]
    float* out2 = out1 + (size_t)NNODE * H;         // [E,H]

    const int smem_node = (TILE_A + TILE_W) * (int)sizeof(__half)
                        + 2 * 16 * SSTRIDE * (int)sizeof(float);              // 69632
    const int smem_edge = (TILE_A + TILE_W) * (int)sizeof(__half)
                        + 2 * BT * (int)sizeof(int)
                        + 2 * 16 * SSTRIDE * (int)sizeof(float);              // 70144
    cudaFuncSetAttribute(k_node_pre, cudaFuncAttributeMaxDynamicSharedMemorySize, smem_node);
    cudaFuncSetAttribute(k_edge,     cudaFuncAttributeMaxDynamicSharedMemorySize, smem_edge);
    cudaFuncSetAttribute(k_node_upd, cudaFuncAttributeMaxDynamicSharedMemorySize, smem_node);

    // Persistent grid for k_edge: exactly (SMs x achieved occupancy) blocks,
    // so every slot runs ceil(NTILES/grid) tiles with zero wave quantization.
    // Host-side queries: deterministic, no allocation, graph-safe.
    int nsm = 148, nblk = 3;
    cudaDeviceGetAttribute(&nsm, cudaDevAttrMultiProcessorCount, 0);
    cudaOccupancyMaxActiveBlocksPerMultiprocessor(&nblk, k_edge, NT, smem_edge);
    if (nblk < 1) nblk = 1;
    int grid_e = nsm * nblk;
    if (grid_e > NTILES) grid_e = NTILES;

    k_prep<<<(5 * H * H + 255) / 256, 256>>>(We, Wn);
    k_node_pre<<<(NNODE + BT - 1) / BT, NT, smem_node>>>(nf, be, bn);
    k_edge<<<grid_e, NT, smem_edge>>>(ef, src, dst, out2);
    k_node_upd<<<(NNODE + BT - 1) / BT, NT, smem_node>>>(nf, out1);
}

// round 17
// speedup vs baseline: 1.4139x; 1.1890x over previous
#include <cuda_runtime.h>
#include <cuda_fp16.h>
#include <cstdint>

// GCNLayer_EdgeCat on GB300 — R17:
//   * g_A / g_C tables stored fp16: per-edge gather bytes halve (dominant L2
//     term in the edge epilogue). Calibrated error ledger: each fp16 source
//     ~1.2e-4; total sqrt(2.4^2+1.2^2+1.2^2)e-4 ~ 2.9e-4 (gate 1e-3).
//   * node kernels persistent (grid = SMs x occupancy, grid-stride) — removes
//     their 1.76-wave quantization, same fix that won R16 for k_edge.
//   We=[We1;We2;We3], Wn=[Wn1;Wn2]:
//     A=nf@We1+be, C=nf@We3, An=nf@Wn1+bn        (k_node_pre)
//     m=ReLU(A[src]+ef@We2+C[dst]); out2=m+ef_hi (k_edge, scatter mean)
//     out1=ReLU(An+mean@Wn2)+nf                  (k_node_upd)
//   GEMMs: single fp16. 3 CTAs/SM everywhere.

#define H        128
#define NNODE    50000
#define NEDGE    800000
#define BT       64           // rows per tile
#define NT       256          // 8 warps: warp = 16 rows x 64 cols
#define NTILES   (NEDGE / BT)             // 12500
#define NTILE_N  ((NNODE + BT - 1) / BT)  // 782
#define STRIDE   136          // fp16 row stride (272B, LDSM conflict-free)
#define SSTRIDE  136          // f32 stage stride
#define TILE_A   (BT * STRIDE)
#define TILE_W   (H * STRIDE)

__device__ __half g_Ah[(size_t)NNODE * H];   // fp16 A table
__device__ __half g_Ch[(size_t)NNODE * H];   // fp16 C table
__device__ float  g_An[(size_t)NNODE * H];   // fp32 (node_upd path)
__device__ float  g_sum[(size_t)NNODE * H];
__device__ float  g_cnt[NNODE];
// 5 weights (We1,We2,We3,Wn1,Wn2): [k][n] row-major fp16.
__device__ __half g_Wimg[5 * H * H];

// ---------- PTX helpers ----------
__device__ __forceinline__ uint32_t smem_u32(const void* p) {
    return (uint32_t)__cvta_generic_to_shared(p);
}
__device__ __forceinline__ void ldsm_x4(uint32_t a[4], uint32_t addr) {
    asm volatile("ldmatrix.sync.aligned.m8n8.x4.shared.b16 {%0,%1,%2,%3}, [%4];"
                 : "=r"(a[0]), "=r"(a[1]), "=r"(a[2]), "=r"(a[3]) : "r"(addr));
}
__device__ __forceinline__ void ldsm_x4_t(uint32_t b[4], uint32_t addr) {
    asm volatile("ldmatrix.sync.aligned.m8n8.x4.trans.shared.b16 {%0,%1,%2,%3}, [%4];"
                 : "=r"(b[0]), "=r"(b[1]), "=r"(b[2]), "=r"(b[3]) : "r"(addr));
}
__device__ __forceinline__ void mma16816(float c[4], const uint32_t a[4], const uint32_t b[2]) {
    asm volatile("mma.sync.aligned.m16n8k16.row.col.f32.f16.f16.f32 "
                 "{%0,%1,%2,%3}, {%4,%5,%6,%7}, {%8,%9}, {%0,%1,%2,%3};"
                 : "+f"(c[0]), "+f"(c[1]), "+f"(c[2]), "+f"(c[3])
                 : "r"(a[0]), "r"(a[1]), "r"(a[2]), "r"(a[3]), "r"(b[0]), "r"(b[1]));
}
__device__ __forceinline__ void red_add_v4(float* p, float4 v) {
    asm volatile("red.global.add.v4.f32 [%0], {%1, %2, %3, %4};"
                 :: "l"(p), "f"(v.x), "f"(v.y), "f"(v.z), "f"(v.w) : "memory");
}

// Store a float4 as 4 fp16 at element offset off.
__device__ __forceinline__ void store_hi(__half* hi, int off, float4 v) {
    *(__half2*)(hi + off)     = __half2{__float2half_rn(v.x), __float2half_rn(v.y)};
    *(__half2*)(hi + off + 2) = __half2{__float2half_rn(v.z), __float2half_rn(v.w)};
}
__device__ __forceinline__ uint32_t pack2(float x, float y) {
    __half2 h{__float2half_rn(x), __float2half_rn(y)};
    return *reinterpret_cast<uint32_t*>(&h);
}
__device__ __forceinline__ float2 unpk(uint32_t u) {
    __half2 h = *reinterpret_cast<__half2*>(&u);
    return make_float2(__half2float(h.x), __half2float(h.y));
}

// 8-warp core: warp tile 16 rows x 64 cols, single-term fp16 (64 MMAs).
__device__ __forceinline__ void mma_core(const __half* sX, const __half* sW,
                                         int lane, int warp, float acc[8][4]) {
    uint32_t x = smem_u32(sX), w = smem_u32(sW);
    int r0 = (warp & 3) * 16, c0 = (warp >> 2) * 64;
    uint32_t aoff = (uint32_t)((r0 + (lane & 15)) * STRIDE + ((lane >> 4) << 3)) * 2;
    uint32_t boff = (uint32_t)((lane & 15) * STRIDE + c0 + ((lane >> 4) << 3)) * 2;
#pragma unroll
    for (int k0 = 0; k0 < H; k0 += 16) {
        uint32_t a[4];
        ldsm_x4(a, x + aoff + k0 * 2);
#pragma unroll
        for (int ntp = 0; ntp < 4; ntp++) {
            uint32_t b[4];
            ldsm_x4_t(b, w + boff + (uint32_t)(k0 * STRIDE + ntp * 16) * 2);
            mma16816(acc[2 * ntp],     a, b + 0);
            mma16816(acc[2 * ntp + 1], a, b + 2);
        }
    }
}

// Stage one 16-row chunk of acc into smem (warps wr==c and wr==c+4 write).
__device__ __forceinline__ void stage_chunk(float* stg, const float acc[8][4],
                                            int c, int wr, int rq, int cb) {
    if (wr == c) {
#pragma unroll
        for (int nt = 0; nt < 8; nt++) {
            int col = cb + nt * 8;
            *(float2*)&stg[rq * SSTRIDE + col] = make_float2(acc[nt][0], acc[nt][1]);
            *(float2*)&stg[(rq + 8) * SSTRIDE + col] = make_float2(acc[nt][2], acc[nt][3]);
        }
    }
}

// Copy a prepped W image ([k][n] 128x128 fp16) into padded smem.
__device__ __forceinline__ void fill_W(__half* sW, int wsel, int t, int nthr) {
    const uint4* w4 = (const uint4*)(g_Wimg + (size_t)wsel * H * H);
    for (int i = t; i < H * H / 8; i += nthr) {       // 2048 uint4
        int row = i >> 4, c8 = (i & 15) * 8;
        *(uint4*)(sW + row * STRIDE + c8) = w4[i];
    }
}

// ---- k_prep: weights -> fp16 [k][n] images (once) ----
__global__ void k_prep(const float* __restrict__ We, const float* __restrict__ Wn) {
    int idx = blockIdx.x * blockDim.x + threadIdx.x;
    if (idx >= 5 * H * H) return;
    int w = idx / (H * H), r = idx % (H * H);
    const float* src = (w < 3) ? (We + w * H * H) : (Wn + (w - 3) * H * H);
    g_Wimg[(size_t)w * H * H + r] = __float2half_rn(src[r]);
}

// ---- k_node_pre (persistent): zero sums; A,C (fp16), An (fp32) ----
__global__ __launch_bounds__(NT, 3)
void k_node_pre(const float* __restrict__ nf,
                const float* __restrict__ be, const float* __restrict__ bn) {
    extern __shared__ __align__(16) __half sm[];
    __half* sX = sm;
    __half* sW = sm + TILE_A;
    float* stage = (float*)(sm + TILE_A + TILE_W);   // 2 x 16 x SSTRIDE
    int t = threadIdx.x, lane = t & 31, warp = t >> 5;

    int rq = lane >> 2, cb = (warp >> 2) * 64 + (lane & 3) * 2;
    int wr = warp & 3;
    int lrow = t >> 4, cg = (t & 15) * 8;        // epilogue ownership
    const int wsel[3] = {0, 2, 3};

    for (int tile = blockIdx.x; tile < NTILE_N; tile += gridDim.x) {
        int nb = tile * BT;

        for (int i = t; i < BT * 32; i += NT) {
            int n = nb + (i >> 5);
            if (n < NNODE) ((float4*)g_sum)[(size_t)n * 32 + (i & 31)] = make_float4(0.f, 0.f, 0.f, 0.f);
        }
        if (t < BT && nb + t < NNODE) g_cnt[nb + t] = 0.f;

        for (int i = t; i < BT * 32; i += NT) {
            int n = nb + (i >> 5);
            float4 v = make_float4(0.f, 0.f, 0.f, 0.f);
            if (n < NNODE) v = ((const float4*)nf)[(size_t)n * 32 + (i & 31)];
            store_hi(sX, (i >> 5) * STRIDE + (i & 31) * 4, v);
        }

        for (int ph = 0; ph < 3; ph++) {
            __syncthreads();                     // sX ready / prev phase consumed
            fill_W(sW, wsel[ph], t, NT);
            __syncthreads();

            float acc[8][4];
#pragma unroll
            for (int i = 0; i < 8; i++) acc[i][0] = acc[i][1] = acc[i][2] = acc[i][3] = 0.f;
            mma_core(sX, sW, lane, warp, acc);

#pragma unroll
            for (int c = 0; c < 4; c++) {
                float* stg = stage + (c & 1) * (16 * SSTRIDE);
                stage_chunk(stg, acc, c, wr, rq, cb);
                __syncthreads();                 // stage(c) ready
                int n = nb + c * 16 + lrow;
                if (n < NNODE) {
                    float4 st0 = *(float4*)&stg[lrow * SSTRIDE + cg];
                    float4 st1 = *(float4*)&stg[lrow * SSTRIDE + cg + 4];
                    if (ph == 0) {               // A = .. + be -> fp16
                        float4 b0 = *(const float4*)&be[cg];
                        float4 b1 = *(const float4*)&be[cg + 4];
                        uint4 u;
                        u.x = pack2(st0.x + b0.x, st0.y + b0.y);
                        u.y = pack2(st0.z + b0.z, st0.w + b0.w);
                        u.z = pack2(st1.x + b1.x, st1.y + b1.y);
                        u.w = pack2(st1.z + b1.z, st1.w + b1.w);
                        *(uint4*)&g_Ah[(size_t)n * H + cg] = u;
                    } else if (ph == 1) {        // C -> fp16
                        uint4 u;
                        u.x = pack2(st0.x, st0.y);
                        u.y = pack2(st0.z, st0.w);
                        u.z = pack2(st1.x, st1.y);
                        u.w = pack2(st1.z, st1.w);
                        *(uint4*)&g_Ch[(size_t)n * H + cg] = u;
                    } else {                     // An = .. + bn -> fp32
                        float4 b0 = *(const float4*)&bn[cg];
                        float4 b1 = *(const float4*)&bn[cg + 4];
                        st0.x += b0.x; st0.y += b0.y; st0.z += b0.z; st0.w += b0.w;
                        st1.x += b1.x; st1.y += b1.y; st1.z += b1.z; st1.w += b1.w;
                        *(float4*)&g_An[(size_t)n * H + cg]     = st0;
                        *(float4*)&g_An[(size_t)n * H + cg + 4] = st1;
                    }
                }
            }
        }
        __syncthreads();                         // epilogue done before sX refill
    }
}

// ---- k_edge (persistent, 3 CTA/SM): fp16 A/C gathers ----
__global__ __launch_bounds__(NT, 3)
void k_edge(const float* __restrict__ ef,
            const int* __restrict__ src, const int* __restrict__ dst,
            float* __restrict__ out2) {
    extern __shared__ __align__(16) __half sm[];
    __half* sX   = sm;
    __half* sW   = sm + TILE_A;
    int*   s_src = (int*)(sm + TILE_A + TILE_W);
    int*   s_dst = s_src + BT;
    float* stage = (float*)(s_dst + BT);         // 2 x 16 x SSTRIDE
    int t = threadIdx.x, lane = t & 31, warp = t >> 5;

    fill_W(sW, 1, t, NT);                        // We2, resident for ALL tiles

    int rq = lane >> 2, cb = (warp >> 2) * 64 + (lane & 3) * 2;
    int wr = warp & 3;
    int lrow = t >> 4, cg = (t & 15) * 8;

    for (int tile = blockIdx.x; tile < NTILES; tile += gridDim.x) {
        int eb = tile * BT;
        if (t < BT) s_src[t] = src[eb + t];
        else if (t < 2 * BT) s_dst[t - BT] = dst[eb + t - BT];
        const float4* ef4 = (const float4*)(ef + (size_t)eb * H);
        for (int i = t; i < BT * 32; i += NT)
            store_hi(sX, (i >> 5) * STRIDE + (i & 31) * 4, ef4[i]);
        __syncthreads();                         // sX (and first-iter sW) ready

        // prefetch chunk 0 gathers (fp16, 16B per table) under the mainloop
        int s_p = s_src[lrow], d_p = s_dst[lrow];
        uint4 ua = *(const uint4*)&g_Ah[(size_t)s_p * H + cg];
        uint4 uc = *(const uint4*)&g_Ch[(size_t)d_p * H + cg];

        float acc[8][4];
#pragma unroll
        for (int i = 0; i < 8; i++) acc[i][0] = acc[i][1] = acc[i][2] = acc[i][3] = 0.f;
        mma_core(sX, sW, lane, warp, acc);

#pragma unroll
        for (int c = 0; c < 4; c++) {
            float* stg = stage + (c & 1) * (16 * SSTRIDE);
            stage_chunk(stg, acc, c, wr, rq, cb);
            __syncthreads();                     // stage(c) ready

            int row = c * 16 + lrow;
            int d = d_p;
            if ((t & 15) == 0) atomicAdd(&g_cnt[d], 1.f);

            float4 st0 = *(float4*)&stg[lrow * SSTRIDE + cg];
            float4 st1 = *(float4*)&stg[lrow * SSTRIDE + cg + 4];
            float2 a01 = unpk(ua.x), a23 = unpk(ua.y), a45 = unpk(ua.z), a67 = unpk(ua.w);
            float2 c01 = unpk(uc.x), c23 = unpk(uc.y), c45 = unpk(uc.z), c67 = unpk(uc.w);
            float4 m0, m1;
            m0.x = fmaxf(st0.x + a01.x + c01.x, 0.f);
            m0.y = fmaxf(st0.y + a01.y + c01.y, 0.f);
            m0.z = fmaxf(st0.z + a23.x + c23.x, 0.f);
            m0.w = fmaxf(st0.w + a23.y + c23.y, 0.f);
            m1.x = fmaxf(st1.x + a45.x + c45.x, 0.f);
            m1.y = fmaxf(st1.y + a45.y + c45.y, 0.f);
            m1.z = fmaxf(st1.z + a67.x + c67.x, 0.f);
            m1.w = fmaxf(st1.w + a67.y + c67.y, 0.f);

            if (c < 3) {                         // next chunk's gathers
                int nrow = (c + 1) * 16 + lrow;
                s_p = s_src[nrow]; d_p = s_dst[nrow];
                ua = *(const uint4*)&g_Ah[(size_t)s_p * H + cg];
                uc = *(const uint4*)&g_Ch[(size_t)d_p * H + cg];
            }

            // ef_hi from sX (fp16; error absorbed by the calibrated budget)
            uint4 uh = *(uint4*)&sX[row * STRIDE + cg];
            const __half2* h2 = (const __half2*)&uh;
            float4 o0, o1;
            o0.x = m0.x + __half2float(h2[0].x);
            o0.y = m0.y + __half2float(h2[0].y);
            o0.z = m0.z + __half2float(h2[1].x);
            o0.w = m0.w + __half2float(h2[1].y);
            o1.x = m1.x + __half2float(h2[2].x);
            o1.y = m1.y + __half2float(h2[2].y);
            o1.z = m1.z + __half2float(h2[3].x);
            o1.w = m1.w + __half2float(h2[3].y);

            *(float4*)&out2[(size_t)(eb + row) * H + cg]     = o0;
            *(float4*)&out2[(size_t)(eb + row) * H + cg + 4] = o1;
            red_add_v4(&g_sum[(size_t)d * H + cg], m0);
            red_add_v4(&g_sum[(size_t)d * H + cg + 4], m1);
        }
        __syncthreads();                         // sX & stage free for next tile
    }
}

// ---- k_node_upd (persistent): out1 = ReLU(An + mean@Wn2) + nf ----
__global__ __launch_bounds__(NT, 3)
void k_node_upd(const float* __restrict__ nf, float* __restrict__ out1) {
    extern __shared__ __align__(16) __half sm[];
    __half* sX = sm;
    __half* sW = sm + TILE_A;
    float* stage = (float*)(sm + TILE_A + TILE_W);
    int t = threadIdx.x, lane = t & 31, warp = t >> 5;

    fill_W(sW, 4, t, NT);                        // Wn2, resident for all tiles

    int rq = lane >> 2, cb = (warp >> 2) * 64 + (lane & 3) * 2;
    int wr = warp & 3;
    int lrow = t >> 4, cg = (t & 15) * 8;

    for (int tile = blockIdx.x; tile < NTILE_N; tile += gridDim.x) {
        int nb = tile * BT;
        for (int i = t; i < BT * 32; i += NT) {
            int n = nb + (i >> 5);
            float4 v = make_float4(0.f, 0.f, 0.f, 0.f);
            if (n < NNODE) {
                v = ((const float4*)g_sum)[(size_t)n * 32 + (i & 31)];
                float inv = 1.0f / fmaxf(g_cnt[n], 1.0f);
                v.x *= inv; v.y *= inv; v.z *= inv; v.w *= inv;
            }
            store_hi(sX, (i >> 5) * STRIDE + (i & 31) * 4, v);
        }
        __syncthreads();                         // sX ready (sW ready 1st iter)

        float acc[8][4];
#pragma unroll
        for (int i = 0; i < 8; i++) acc[i][0] = acc[i][1] = acc[i][2] = acc[i][3] = 0.f;
        mma_core(sX, sW, lane, warp, acc);

#pragma unroll
        for (int c = 0; c < 4; c++) {
            float* stg = stage + (c & 1) * (16 * SSTRIDE);
            stage_chunk(stg, acc, c, wr, rq, cb);
            __syncthreads();
            int n = nb + c * 16 + lrow;
            if (n < NNODE) {
                float4 st0 = *(float4*)&stg[lrow * SSTRIDE + cg];
                float4 st1 = *(float4*)&stg[lrow * SSTRIDE + cg + 4];
                float4 an0 = *(const float4*)&g_An[(size_t)n * H + cg];
                float4 an1 = *(const float4*)&g_An[(size_t)n * H + cg + 4];
                float4 nv0 = *(const float4*)&nf[(size_t)n * H + cg];
                float4 nv1 = *(const float4*)&nf[(size_t)n * H + cg + 4];
                float4 o0, o1;
                o0.x = fmaxf(st0.x + an0.x, 0.f) + nv0.x;
                o0.y = fmaxf(st0.y + an0.y, 0.f) + nv0.y;
                o0.z = fmaxf(st0.z + an0.z, 0.f) + nv0.z;
                o0.w = fmaxf(st0.w + an0.w, 0.f) + nv0.w;
                o1.x = fmaxf(st1.x + an1.x, 0.f) + nv1.x;
                o1.y = fmaxf(st1.y + an1.y, 0.f) + nv1.y;
                o1.z = fmaxf(st1.z + an1.z, 0.f) + nv1.z;
                o1.w = fmaxf(st1.w + an1.w, 0.f) + nv1.w;
                *(float4*)&out1[(size_t)n * H + cg]     = o0;
                *(float4*)&out1[(size_t)n * H + cg + 4] = o1;
            }
        }
        __syncthreads();                         // epilogue done before sX refill
    }
}

extern "C" void kernel_launch(void* const* d_in, const int* in_sizes, int n_in,
                              void* d_out, int out_size) {
    const float* nf  = (const float*)d_in[0];
    const float* ef  = (const float*)d_in[1];
    const int*   src = (const int*)d_in[2];
    const int*   dst = (const int*)d_in[3];
    const float* We  = (const float*)d_in[4];
    const float* be  = (const float*)d_in[5];
    const float* Wn  = (const float*)d_in[6];
    const float* bn  = (const float*)d_in[7];
    float* out1 = (float*)d_out;                    // [N,H]
    float* out2 = out1 + (size_t)NNODE * H;         // [E,H]

    const int smem_node = (TILE_A + TILE_W) * (int)sizeof(__half)
                        + 2 * 16 * SSTRIDE * (int)sizeof(float);              // 69632
    const int smem_edge = (TILE_A + TILE_W) * (int)sizeof(__half)
                        + 2 * BT * (int)sizeof(int)
                        + 2 * 16 * SSTRIDE * (int)sizeof(float);              // 70144
    cudaFuncSetAttribute(k_node_pre, cudaFuncAttributeMaxDynamicSharedMemorySize, smem_node);
    cudaFuncSetAttribute(k_edge,     cudaFuncAttributeMaxDynamicSharedMemorySize, smem_edge);
    cudaFuncSetAttribute(k_node_upd, cudaFuncAttributeMaxDynamicSharedMemorySize, smem_node);

    // Persistent grids: exactly (SMs x achieved occupancy) blocks per kernel.
    // Host-side queries: deterministic, no allocation, graph-safe.
    int nsm = 148, nbe = 3, nbn = 3;
    cudaDeviceGetAttribute(&nsm, cudaDevAttrMultiProcessorCount, 0);
    cudaOccupancyMaxActiveBlocksPerMultiprocessor(&nbe, k_edge, NT, smem_edge);
    cudaOccupancyMaxActiveBlocksPerMultiprocessor(&nbn, k_node_pre, NT, smem_node);
    if (nbe < 1) nbe = 1;
    if (nbn < 1) nbn = 1;
    int grid_e = nsm * nbe; if (grid_e > NTILES)  grid_e = NTILES;
    int grid_n = nsm * nbn; if (grid_n > NTILE_N) grid_n = NTILE_N;

    k_prep<<<(5 * H * H + 255) / 256, 256>>>(We, Wn);
    k_node_pre<<<grid_n, NT, smem_node>>>(nf, be, bn);
    k_edge<<<grid_e, NT, smem_edge>>>(ef, src, dst, out2);
    k_node_upd<<<grid_n, NT, smem_node>>>(nf, out1);
}